// round 2
// baseline (speedup 1.0000x reference)
#include <cuda_runtime.h>
#include <cuda_bf16.h>
#include <cstdint>

#define B 4096

// ---------------- scratch (device globals; no allocation allowed) ----------------
__device__ float g_out1[B * 32 * 14 * 14];   // after conv1 block
__device__ float g_out2[B * 32 * 7 * 7];     // after conv2 block
__device__ float g_out3[B * 32 * 3 * 3];     // after conv3 block (pre-BN)
__device__ float g_w2r[32 * 9 * 32];         // cw2 rearranged [ic][k][oc]
__device__ float g_w3r[32 * 9 * 32];         // cw3 rearranged [ic][k][oc]
__device__ float g_stats[64];                // sum[32], sumsq[32]
__device__ float g_scale[32], g_shift[32];   // BN affine
__device__ float g_Wc[3 * 288 * 10];         // composed expert weights
__device__ float g_bc[3 * 10];               // composed expert bias

// ---------------- prep: rearrange conv2/conv3 weights, zero stats ----------------
__global__ void prep_kernel(const float* __restrict__ cw2, const float* __restrict__ cw3) {
    int i = blockIdx.x * blockDim.x + threadIdx.x;
    if (i < 64) g_stats[i] = 0.f;
    if (i < 9216) {
        int oc = i / 288;
        int rem = i - oc * 288;      // ic*9 + k
        g_w2r[rem * 32 + oc] = cw2[i];
        g_w3r[rem * 32 + oc] = cw3[i];
    }
}

// ---------------- conv1 (1->32) + relu + pool : [B,1,28,28] -> [B,32,14,14] ------
__global__ void conv1_kernel(const float* __restrict__ x,
                             const float* __restrict__ cw1,
                             const float* __restrict__ cb1) {
    __shared__ float w1s[288];
    __shared__ float b1s[32];
    int tid = threadIdx.x;
    for (int i = tid; i < 288; i += 256) w1s[i] = cw1[i];
    if (tid < 32) b1s[tid] = cb1[tid];
    __syncthreads();

    int idx = blockIdx.x * 256 + tid;          // 0 .. B*196-1 (exact)
    int b = idx / 196;
    int pos = idx - b * 196;
    int ph = pos / 14, pw = pos - ph * 14;

    // 4x4 input patch, rows 2ph-1..2ph+2, cols 2pw-1..2pw+2, zero padded
    float p[4][4];
    const float* xb = x + b * 784;
#pragma unroll
    for (int r = 0; r < 4; r++) {
        int ir = 2 * ph - 1 + r;
#pragma unroll
        for (int c = 0; c < 4; c++) {
            int ic = 2 * pw - 1 + c;
            p[r][c] = (ir >= 0 && ir < 28 && ic >= 0 && ic < 28) ? xb[ir * 28 + ic] : 0.f;
        }
    }

    float* dst = g_out1 + b * 6272 + pos;      // [b][oc][196]
#pragma unroll 4
    for (int oc = 0; oc < 32; oc++) {
        float a0 = 0.f, a1 = 0.f, a2 = 0.f, a3 = 0.f;
#pragma unroll
        for (int kh = 0; kh < 3; kh++)
#pragma unroll
            for (int kw = 0; kw < 3; kw++) {
                float w = w1s[oc * 9 + kh * 3 + kw];
                a0 += p[kh][kw] * w;
                a1 += p[kh][kw + 1] * w;
                a2 += p[kh + 1][kw] * w;
                a3 += p[kh + 1][kw + 1] * w;
            }
        float v = fmaxf(fmaxf(a0, a1), fmaxf(a2, a3)) + b1s[oc];
        dst[oc * 196] = fmaxf(v, 0.f);
    }
}

// ---------------- conv2 (32->32) + relu + pool : [B,32,14,14] -> [B,32,7,7] ------
__global__ void __launch_bounds__(224) conv2_kernel(const float* __restrict__ cb2) {
    __shared__ float sIn[32 * 16 * 16];        // padded [ic][16][16]
    int b = blockIdx.x;
    int tid = threadIdx.x;
    for (int i = tid; i < 8192; i += 224) sIn[i] = 0.f;
    __syncthreads();
    const float* src = g_out1 + b * 6272;
    for (int i = tid; i < 6272; i += 224) {
        int ic = i / 196;
        int rem = i - ic * 196;
        int r = rem / 14, c = rem - r * 14;
        sIn[ic * 256 + (r + 1) * 16 + (c + 1)] = src[i];
    }
    __syncthreads();

    if (tid < 196) {
        int ocg = tid / 49;
        int pos = tid - ocg * 49;
        int ph = pos / 7, pw = pos - ph * 7;

        float acc[8][4];
#pragma unroll
        for (int o = 0; o < 8; o++)
#pragma unroll
            for (int q = 0; q < 4; q++) acc[o][q] = 0.f;

        const float* sbase = sIn + (2 * ph) * 16 + 2 * pw;  // halo already +1 offset
        for (int ic = 0; ic < 32; ic++) {
            const float* sp = sbase + ic * 256;
            float p[4][4];
#pragma unroll
            for (int r = 0; r < 4; r++) {
                float2 u = *(const float2*)(sp + r * 16);
                float2 v = *(const float2*)(sp + r * 16 + 2);
                p[r][0] = u.x; p[r][1] = u.y; p[r][2] = v.x; p[r][3] = v.y;
            }
            const float4* wp = (const float4*)(g_w2r + ic * 288 + ocg * 8);
#pragma unroll
            for (int kh = 0; kh < 3; kh++)
#pragma unroll
                for (int kw = 0; kw < 3; kw++) {
                    int kidx = kh * 3 + kw;
                    float4 wa = __ldg(&wp[kidx * 8]);
                    float4 wb = __ldg(&wp[kidx * 8 + 1]);
#pragma unroll
                    for (int dh = 0; dh < 2; dh++)
#pragma unroll
                        for (int dw = 0; dw < 2; dw++) {
                            float iv = p[kh + dh][kw + dw];
                            int q = dh * 2 + dw;
                            acc[0][q] += iv * wa.x; acc[1][q] += iv * wa.y;
                            acc[2][q] += iv * wa.z; acc[3][q] += iv * wa.w;
                            acc[4][q] += iv * wb.x; acc[5][q] += iv * wb.y;
                            acc[6][q] += iv * wb.z; acc[7][q] += iv * wb.w;
                        }
                }
        }
        float* dst = g_out2 + (b * 32 + ocg * 8) * 49 + pos;
#pragma unroll
        for (int o = 0; o < 8; o++) {
            float v = fmaxf(fmaxf(acc[o][0], acc[o][1]), fmaxf(acc[o][2], acc[o][3]))
                      + __ldg(&cb2[ocg * 8 + o]);
            dst[o * 49] = fmaxf(v, 0.f);
        }
    }
}

// ---------------- conv3 (32->32) + relu + pool(floor) + BN-stat atomics ----------
// [B,32,7,7] -> [B,32,3,3]; only 6x6 conv positions needed (row/col 6 dropped).
#define C3_NB 3
__global__ void __launch_bounds__(128) conv3_kernel(const float* __restrict__ cb3) {
    __shared__ float sm[C3_NB * 32 * 9 * 12];  // padded [im][ic][9][12], 41472 B
    __shared__ float ssum[32], ssq[32];
    int tid = threadIdx.x;
    int b0 = blockIdx.x * C3_NB;

    for (int i = tid; i < C3_NB * 3456; i += 128) sm[i] = 0.f;
    if (tid < 32) { ssum[tid] = 0.f; ssq[tid] = 0.f; }
    __syncthreads();

    for (int idx = tid; idx < C3_NB * 1568; idx += 128) {
        int im = idx / 1568;
        int j = idx - im * 1568;
        int img = b0 + im;
        if (img < B) {
            int ic = j / 49;
            int rem = j - ic * 49;
            int r = rem / 7, c = rem - r * 7;
            sm[im * 3456 + ic * 108 + (r + 1) * 12 + (c + 1)] = g_out2[img * 1568 + j];
        }
    }
    __syncthreads();

    if (tid < C3_NB * 36) {
        int im = tid / 36;
        int img = b0 + im;
        if (img < B) {
            int rem = tid - im * 36;
            int ocg = rem / 9;
            int pos = rem - ocg * 9;
            int ph = pos / 3, pw = pos - ph * 3;

            float acc[8][4];
#pragma unroll
            for (int o = 0; o < 8; o++)
#pragma unroll
                for (int q = 0; q < 4; q++) acc[o][q] = 0.f;

            const float* sbase = sm + im * 3456 + (2 * ph) * 12 + 2 * pw;
            for (int ic = 0; ic < 32; ic++) {
                const float* sp = sbase + ic * 108;
                float p[4][4];
#pragma unroll
                for (int r = 0; r < 4; r++) {
                    float2 u = *(const float2*)(sp + r * 12);
                    float2 v = *(const float2*)(sp + r * 12 + 2);
                    p[r][0] = u.x; p[r][1] = u.y; p[r][2] = v.x; p[r][3] = v.y;
                }
                const float4* wp = (const float4*)(g_w3r + ic * 288 + ocg * 8);
#pragma unroll
                for (int kh = 0; kh < 3; kh++)
#pragma unroll
                    for (int kw = 0; kw < 3; kw++) {
                        int kidx = kh * 3 + kw;
                        float4 wa = __ldg(&wp[kidx * 8]);
                        float4 wb = __ldg(&wp[kidx * 8 + 1]);
#pragma unroll
                        for (int dh = 0; dh < 2; dh++)
#pragma unroll
                            for (int dw = 0; dw < 2; dw++) {
                                float iv = p[kh + dh][kw + dw];
                                int q = dh * 2 + dw;
                                acc[0][q] += iv * wa.x; acc[1][q] += iv * wa.y;
                                acc[2][q] += iv * wa.z; acc[3][q] += iv * wa.w;
                                acc[4][q] += iv * wb.x; acc[5][q] += iv * wb.y;
                                acc[6][q] += iv * wb.z; acc[7][q] += iv * wb.w;
                            }
                    }
            }
#pragma unroll
            for (int o = 0; o < 8; o++) {
                int oc = ocg * 8 + o;
                float v = fmaxf(fmaxf(acc[o][0], acc[o][1]), fmaxf(acc[o][2], acc[o][3]))
                          + __ldg(&cb3[oc]);
                v = fmaxf(v, 0.f);
                g_out3[img * 288 + oc * 9 + pos] = v;
                atomicAdd(&ssum[oc], v);
                atomicAdd(&ssq[oc], v * v);
            }
        }
    }
    __syncthreads();
    if (tid < 32) {
        atomicAdd(&g_stats[tid], ssum[tid]);
        atomicAdd(&g_stats[32 + tid], ssq[tid]);
    }
}

// ---------------- BN finalize -> scale/shift per channel ------------------------
__global__ void bn_finalize_kernel(const float* __restrict__ bn_g,
                                   const float* __restrict__ bn_b) {
    int c = threadIdx.x;
    if (c < 32) {
        const float inv_n = 1.0f / (float)(B * 9);
        float m = g_stats[c] * inv_n;
        float var = g_stats[32 + c] * inv_n - m * m;
        float sc = bn_g[c] * rsqrtf(var + 1e-5f);
        g_scale[c] = sc;
        g_shift[c] = bn_b[c] - m * sc;
    }
}

// ---------------- compose the 3 chained expert linears per action ---------------
__global__ void compose_kernel(const float* __restrict__ ew1, const float* __restrict__ eb1,
                               const float* __restrict__ ew2, const float* __restrict__ eb2,
                               const float* __restrict__ ew3, const float* __restrict__ eb3) {
    __shared__ float E3s[1280];   // [128][10]
    __shared__ float C1s[1280];   // E2@E3  [128][10]
    int a = blockIdx.x;
    int tid = threadIdx.x;
    for (int i = tid; i < 1280; i += 128) E3s[i] = ew3[a * 1280 + i];
    __syncthreads();
    {
        float s[10];
#pragma unroll
        for (int o = 0; o < 10; o++) s[o] = 0.f;
        const float* e2r = ew2 + a * 16384 + tid * 128;
        for (int j = 0; j < 128; j++) {
            float e = e2r[j];
#pragma unroll
            for (int o = 0; o < 10; o++) s[o] += e * E3s[j * 10 + o];
        }
#pragma unroll
        for (int o = 0; o < 10; o++) C1s[tid * 10 + o] = s[o];
    }
    __syncthreads();
    if (tid < 10) {
        float bb = eb3[a * 10 + tid];
        for (int i = 0; i < 128; i++) {
            bb += eb2[a * 128 + i] * E3s[i * 10 + tid];
            bb += eb1[a * 128 + i] * C1s[i * 10 + tid];
        }
        g_bc[a * 10 + tid] = bb;
    }
    for (int k = tid; k < 288; k += 128) {
        float s[10];
#pragma unroll
        for (int o = 0; o < 10; o++) s[o] = 0.f;
        const float* e1r = ew1 + a * 36864 + k * 128;
        for (int i = 0; i < 128; i++) {
            float e = e1r[i];
#pragma unroll
            for (int o = 0; o < 10; o++) s[o] += e * C1s[i * 10 + o];
        }
#pragma unroll
        for (int o = 0; o < 10; o++) g_Wc[(a * 288 + k) * 10 + o] = s[o];
    }
}

// ---------------- MLP + argmax routing + composed selection ---------------------
// 8 warps/block, 2 examples per warp => 16 examples/block, grid 256.
__global__ void __launch_bounds__(256) mlp_kernel(
    const float* __restrict__ pw1, const float* __restrict__ pb1,
    const float* __restrict__ pw2, const float* __restrict__ pb2,
    const float* __restrict__ pw3, const float* __restrict__ pb3,
    float* __restrict__ out, int write_actions) {
    __shared__ float ys[8 * 2 * 288];
    __shared__ float hA[8 * 2 * 128];
    __shared__ float hB[8 * 2 * 128];
    int w = threadIdx.x >> 5;
    int lane = threadIdx.x & 31;
    float* yw = ys + w * 576;
    float* ha = hA + w * 256;
    float* hb = hB + w * 256;
    int e0 = blockIdx.x * 16 + w * 2;

    // load + BN
    for (int idx = lane; idx < 576; idx += 32) {
        int e = idx / 288;
        int k = idx - e * 288;
        int c = k / 9;
        yw[idx] = g_out3[(e0 + e) * 288 + k] * g_scale[c] + g_shift[c];
    }
    __syncwarp();

    // layer1: 288 -> 128, relu
    {
        float acc[2][4];
#pragma unroll
        for (int m = 0; m < 4; m++) {
            float bv = __ldg(&pb1[lane + 32 * m]);
            acc[0][m] = bv; acc[1][m] = bv;
        }
        for (int k = 0; k < 288; k++) {
            const float* wr = pw1 + k * 128 + lane;
            float w0 = wr[0], w1 = wr[32], w2 = wr[64], w3 = wr[96];
            float y0 = yw[k], y1 = yw[288 + k];
            acc[0][0] += y0 * w0; acc[0][1] += y0 * w1; acc[0][2] += y0 * w2; acc[0][3] += y0 * w3;
            acc[1][0] += y1 * w0; acc[1][1] += y1 * w1; acc[1][2] += y1 * w2; acc[1][3] += y1 * w3;
        }
#pragma unroll
        for (int e = 0; e < 2; e++)
#pragma unroll
            for (int m = 0; m < 4; m++)
                ha[e * 128 + lane + 32 * m] = fmaxf(acc[e][m], 0.f);
    }
    __syncwarp();

    // layer2: 128 -> 128, relu
    {
        float acc[2][4];
#pragma unroll
        for (int m = 0; m < 4; m++) {
            float bv = __ldg(&pb2[lane + 32 * m]);
            acc[0][m] = bv; acc[1][m] = bv;
        }
        for (int k = 0; k < 128; k++) {
            const float* wr = pw2 + k * 128 + lane;
            float w0 = wr[0], w1 = wr[32], w2 = wr[64], w3 = wr[96];
            float y0 = ha[k], y1 = ha[128 + k];
            acc[0][0] += y0 * w0; acc[0][1] += y0 * w1; acc[0][2] += y0 * w2; acc[0][3] += y0 * w3;
            acc[1][0] += y1 * w0; acc[1][1] += y1 * w1; acc[1][2] += y1 * w2; acc[1][3] += y1 * w3;
        }
#pragma unroll
        for (int e = 0; e < 2; e++)
#pragma unroll
            for (int m = 0; m < 4; m++)
                hb[e * 128 + lane + 32 * m] = fmaxf(acc[e][m], 0.f);
    }
    __syncwarp();

    // layer3 logits + argmax + composed selection, per example
    for (int e = 0; e < 2; e++) {
        float p0 = 0.f, p1 = 0.f, p2 = 0.f;
#pragma unroll
        for (int kk = 0; kk < 4; kk++) {
            int k = lane + 32 * kk;
            float hv = hb[e * 128 + k];
            const float* wr = pw3 + k * 3;
            p0 += hv * wr[0]; p1 += hv * wr[1]; p2 += hv * wr[2];
        }
#pragma unroll
        for (int off = 16; off > 0; off >>= 1) {
            p0 += __shfl_down_sync(0xffffffffu, p0, off);
            p1 += __shfl_down_sync(0xffffffffu, p1, off);
            p2 += __shfl_down_sync(0xffffffffu, p2, off);
        }
        int a = 0;
        if (lane == 0) {
            p0 += __ldg(&pb3[0]); p1 += __ldg(&pb3[1]); p2 += __ldg(&pb3[2]);
            float best = p0;
            if (p1 > best) { best = p1; a = 1; }
            if (p2 > best) { a = 2; }
        }
        a = __shfl_sync(0xffffffffu, a, 0);

        float po[10];
#pragma unroll
        for (int o = 0; o < 10; o++) po[o] = 0.f;
        const float* Wb = g_Wc + a * 2880;
        const float* ye = yw + e * 288;
#pragma unroll
        for (int kk = 0; kk < 9; kk++) {
            int k = lane + 32 * kk;
            float yv = ye[k];
            const float* wr = Wb + k * 10;
#pragma unroll
            for (int o = 0; o < 10; o++) po[o] += yv * wr[o];
        }
#pragma unroll
        for (int off = 16; off > 0; off >>= 1) {
#pragma unroll
            for (int o = 0; o < 10; o++) po[o] += __shfl_down_sync(0xffffffffu, po[o], off);
        }
        if (lane == 0) {
            int g = e0 + e;
#pragma unroll
            for (int o = 0; o < 10; o++) out[g * 10 + o] = po[o] + g_bc[a * 10 + o];
            if (write_actions) out[B * 10 + g] = (float)a;
        }
    }
}

// ---------------- launch ---------------------------------------------------------
extern "C" void kernel_launch(void* const* d_in, const int* in_sizes, int n_in,
                              void* d_out, int out_size) {
    const float* x    = (const float*)d_in[0];
    const float* cw1  = (const float*)d_in[1];
    const float* cb1  = (const float*)d_in[2];
    const float* cw2  = (const float*)d_in[3];
    const float* cb2  = (const float*)d_in[4];
    const float* cw3  = (const float*)d_in[5];
    const float* cb3  = (const float*)d_in[6];
    const float* bn_g = (const float*)d_in[7];
    const float* bn_b = (const float*)d_in[8];
    const float* pw1  = (const float*)d_in[9];
    const float* pb1  = (const float*)d_in[10];
    const float* pw2  = (const float*)d_in[11];
    const float* pb2  = (const float*)d_in[12];
    const float* pw3  = (const float*)d_in[13];
    const float* pb3  = (const float*)d_in[14];
    const float* ew1  = (const float*)d_in[15];
    const float* eb1  = (const float*)d_in[16];
    const float* ew2  = (const float*)d_in[17];
    const float* eb2  = (const float*)d_in[18];
    const float* ew3  = (const float*)d_in[19];
    const float* eb3  = (const float*)d_in[20];
    float* out = (float*)d_out;
    int write_actions = (out_size >= B * 10 + B) ? 1 : 0;

    prep_kernel<<<36, 256>>>(cw2, cw3);
    conv1_kernel<<<(B * 196) / 256, 256>>>(x, cw1, cb1);
    conv2_kernel<<<B, 224>>>(cb2);
    conv3_kernel<<<(B + C3_NB - 1) / C3_NB, 128>>>(cb3);
    bn_finalize_kernel<<<1, 32>>>(bn_g, bn_b);
    compose_kernel<<<3, 128>>>(ew1, eb1, ew2, eb2, ew3, eb3);
    mlp_kernel<<<B / 16, 256>>>(pw1, pb1, pw2, pb2, pw3, pb3, out, write_actions);
}

// round 4
// speedup vs baseline: 1.0129x; 1.0129x over previous
#include <cuda_runtime.h>
#include <cuda_bf16.h>
#include <cuda_fp16.h>
#include <cstdint>

#define B 4096

__device__ float g_out1[B * 6272];   // conv1 out, [b][pos][ic]
__device__ float g_out3[B * 288];    // conv3 out (pre-BN), [b][oc*9+pos]
__device__ float g_stats[64];
__device__ float g_scale[32], g_shift[32];
__device__ float g_Wc[3 * 288 * 10];
__device__ float g_bc[30];

// ---------------- portable tensor-core helpers (sm_80+ PTX only) ---------------
__device__ __forceinline__ uint32_t smem_u32(const void* p) {
    uint32_t a;
    asm("{ .reg .u64 t; cvta.to.shared.u64 t, %1; cvt.u32.u64 %0, t; }" : "=r"(a) : "l"(p));
    return a;
}
__device__ __forceinline__ void ldsm4(uint32_t& a0, uint32_t& a1, uint32_t& a2, uint32_t& a3, uint32_t addr) {
    asm volatile("ldmatrix.sync.aligned.m8n8.x4.shared.b16 {%0,%1,%2,%3}, [%4];"
                 : "=r"(a0), "=r"(a1), "=r"(a2), "=r"(a3) : "r"(addr));
}
__device__ __forceinline__ void ldsm2(uint32_t& b0, uint32_t& b1, uint32_t addr) {
    asm volatile("ldmatrix.sync.aligned.m8n8.x2.shared.b16 {%0,%1}, [%2];"
                 : "=r"(b0), "=r"(b1) : "r"(addr));
}
__device__ __forceinline__ void mma16816(float* c, uint32_t a0, uint32_t a1, uint32_t a2, uint32_t a3,
                                         uint32_t b0, uint32_t b1) {
    asm volatile("mma.sync.aligned.m16n8k16.row.col.f32.f16.f16.f32 "
                 "{%0,%1,%2,%3}, {%4,%5,%6,%7}, {%8,%9}, {%0,%1,%2,%3};"
                 : "+f"(c[0]), "+f"(c[1]), "+f"(c[2]), "+f"(c[3])
                 : "r"(a0), "r"(a1), "r"(a2), "r"(a3), "r"(b0), "r"(b1));
}
__device__ __forceinline__ void split_store(char* smem, uint32_t oh, uint32_t ol, float v) {
    __half h = __float2half_rn(v);
    __half l = __float2half_rn(v - __half2float(h));
    *(__half*)(smem + oh) = h;
    *(__half*)(smem + ol) = l;
}

__global__ void zero_stats_kernel() { if (threadIdx.x < 64) g_stats[threadIdx.x] = 0.f; }

// ---------------- conv1 (1->32)+relu+pool -> [b][pos][ic] -----------------------
__global__ void conv1_kernel(const float* __restrict__ x,
                             const float* __restrict__ cw1,
                             const float* __restrict__ cb1) {
    __shared__ float w1s[288], b1s[32];
    int tid = threadIdx.x;
    for (int i = tid; i < 288; i += 256) w1s[i] = cw1[i];
    if (tid < 32) b1s[tid] = cb1[tid];
    __syncthreads();
    int idx = blockIdx.x * 256 + tid;
    int b = idx / 196, pos = idx - b * 196;
    int ph = pos / 14, pw = pos - ph * 14;
    float p[4][4];
    const float* xb = x + b * 784;
#pragma unroll
    for (int r = 0; r < 4; r++) {
        int ir = 2 * ph - 1 + r;
#pragma unroll
        for (int c = 0; c < 4; c++) {
            int ic = 2 * pw - 1 + c;
            p[r][c] = (ir >= 0 && ir < 28 && ic >= 0 && ic < 28) ? xb[ir * 28 + ic] : 0.f;
        }
    }
    float vals[32];
#pragma unroll 4
    for (int oc = 0; oc < 32; oc++) {
        float a0 = 0.f, a1 = 0.f, a2 = 0.f, a3 = 0.f;
#pragma unroll
        for (int kh = 0; kh < 3; kh++)
#pragma unroll
            for (int kw = 0; kw < 3; kw++) {
                float w = w1s[oc * 9 + kh * 3 + kw];
                a0 += p[kh][kw] * w;     a1 += p[kh][kw + 1] * w;
                a2 += p[kh + 1][kw] * w; a3 += p[kh + 1][kw + 1] * w;
            }
        vals[oc] = fmaxf(fmaxf(fmaxf(a0, a1), fmaxf(a2, a3)) + b1s[oc], 0.f);
    }
    float4* dst4 = (float4*)(g_out1 + b * 6272 + pos * 32);
#pragma unroll
    for (int j = 0; j < 8; j++)
        dst4[j] = make_float4(vals[4 * j], vals[4 * j + 1], vals[4 * j + 2], vals[4 * j + 3]);
}

// ---------------- fused conv2+conv3 via mma.sync (persistent) -------------------
#define SAS 104                                   // A/B row stride in elems (208 B)
#define SM_SAH 1024
#define SM_SAL (SM_SAH + 256 * SAS * 2)           // 54272
#define SM_SB  (SM_SAL + 256 * SAS * 2)           // 107520
#define SB_MAT (32 * SAS * 2)                     // 6656
#define SM_C2  (SM_SB + 12 * SB_MAT)              // 187392
#define SM_PO  (SM_C2 + 196 * 33 * 4)             // 213264
#define SM_C3  (SM_PO + 49 * 33 * 4)              // 219732
#define SM_TOTAL (SM_C3 + 36 * 33 * 4 + 28)       // 224512

__global__ void __launch_bounds__(256, 1) conv23_kernel(
    const float* __restrict__ cw2, const float* __restrict__ cb2,
    const float* __restrict__ cw3, const float* __restrict__ cb3) {
    extern __shared__ char smem[];
    uint32_t sb = smem_u32(smem);
    int tid = threadIdx.x, wid = tid >> 5, lane = tid & 31;
    float* ssum = (float*)(smem + 64);
    float* ssq  = (float*)(smem + 192);
    float* C2 = (float*)(smem + SM_C2);
    float* PO = (float*)(smem + SM_PO);
    float* C3 = (float*)(smem + SM_C3);

    if (tid < 32) { ssum[tid] = 0.f; ssq[tid] = 0.f; }
    // zero whole A region once (padding rows stay zero forever)
    for (int i = tid; i < 6656; i += 256)
        ((float4*)(smem + SM_SAH))[i] = make_float4(0.f, 0.f, 0.f, 0.f);
    __syncthreads();
    // fill B (weights, hi/lo), layout [conv][kh][split][oc][k], k = kw*32+ic
    for (int idx = tid; idx < 18432; idx += 256) {
        int conv = idx / 9216, r = idx % 9216;
        int kh = r / 3072; r %= 3072;
        int oc = r / 96, k = r % 96;
        int kw = k >> 5, ic = k & 31;
        float w = __ldg(&(conv ? cw3 : cw2)[oc * 288 + ic * 9 + kh * 3 + kw]);
        uint32_t base = SM_SB + ((conv * 3 + kh) * 2) * SB_MAT + (oc * SAS + k) * 2;
        split_store(smem, base, base + SB_MAT, w);
    }
    // zero B padding cols 96..103
    for (int idx = tid; idx < 12 * 256; idx += 256) {
        int mat = idx / 256, r = idx % 256;
        int oc = r / 8, j = r % 8;
        *(__half*)(smem + SM_SB + mat * SB_MAT + (oc * SAS + 96 + j) * 2) = __float2half(0.f);
    }
    __syncthreads();

    int g = lane >> 2, tg = lane & 3;
    uint32_t a_r = (uint32_t)(lane & 15), a_c = (uint32_t)((lane >> 4) * 8);
    uint32_t b_r = (uint32_t)(lane & 7),  b_c = (uint32_t)(lane & 8);
    float lsum = 0.f, lsq = 0.f, lsum2 = 0.f, lsq2 = 0.f;
    int myoc = tid / 9, myoc2 = (tid + 256) / 9;

    for (int it = 0; it < 28; it++) {
        int img = blockIdx.x + 148 * it;
        if (img >= B) break;
        __syncthreads();   // SA free of prior readers
        // A2 fill: rows P*16+Q (P=1..14, Q=0..13), lane = ic
        const float* gin = g_out1 + img * 6272;
        for (int t = wid; t < 196; t += 8) {
            int P = t / 14 + 1, Q = t - (t / 14) * 14;
            int row = P * 16 + Q;
#pragma unroll
            for (int kw = 0; kw < 3; kw++) {
                int c = Q + kw - 1;
                float v = (c >= 0 && c < 14) ? gin[((P - 1) * 14 + c) * 32 + lane] : 0.f;
                uint32_t off = (uint32_t)(row * SAS + kw * 32 + lane) * 2;
                split_store(smem, SM_SAH + off, SM_SAL + off, v);
            }
        }
        __syncthreads();
        // conv2 mma: m-tiles 1..14 (4 n-tiles each)
        for (int m = 1 + wid; m <= 14; m += 8) {
            float acc[2][4][4];
#pragma unroll
            for (int bk = 0; bk < 2; bk++)
#pragma unroll
                for (int n = 0; n < 4; n++)
#pragma unroll
                    for (int i = 0; i < 4; i++) acc[bk][n][i] = 0.f;
#pragma unroll
            for (int kh = 0; kh < 3; kh++) {
                int R0 = m * 16 + (kh - 1) * 16;
#pragma unroll
                for (int s = 0; s < 3; s++) {
                    uint32_t Abase = sb + ((s == 2) ? SM_SAL : SM_SAH);
                    uint32_t Bmat = sb + SM_SB + (uint32_t)((kh * 2 + (s == 1 ? 1 : 0))) * SB_MAT;
#pragma unroll
                    for (int j = 0; j < 6; j++) {
                        uint32_t aaddr = Abase + (((uint32_t)R0 + a_r) * SAS + j * 16 + a_c) * 2;
                        uint32_t a0, a1, a2, a3;
                        ldsm4(a0, a1, a2, a3, aaddr);
#pragma unroll
                        for (int n = 0; n < 4; n++) {
                            uint32_t baddr = Bmat + ((n * 8 + b_r) * SAS + j * 16 + b_c) * 2;
                            uint32_t b0, b1;
                            ldsm2(b0, b1, baddr);
                            mma16816(acc[j & 1][n], a0, a1, a2, a3, b0, b1);
                        }
                    }
                }
            }
#pragma unroll
            for (int n = 0; n < 4; n++) {
#pragma unroll
                for (int i = 0; i < 4; i++) acc[0][n][i] += acc[1][n][i];
                int col = n * 8 + 2 * tg;
                int pos = (m - 1) * 14 + g;          // Q = g < 8 always valid
                C2[pos * 33 + col] = acc[0][n][0];
                C2[pos * 33 + col + 1] = acc[0][n][1];
                if (g < 6) {                          // Q = g+8 valid iff < 14
                    int pos2 = pos + 8;
                    C2[pos2 * 33 + col] = acc[0][n][2];
                    C2[pos2 * 33 + col + 1] = acc[0][n][3];
                }
            }
        }
        __syncthreads();
        // pool conv2 -> PO (bias+relu)
        for (int idx = tid; idx < 1568; idx += 256) {
            int oc = idx & 31, pos = idx >> 5;
            int pr = pos / 7, pc = pos - pr * 7;
            const float* c0 = C2 + ((2 * pr) * 14 + 2 * pc) * 33 + oc;
            float v = fmaxf(fmaxf(c0[0], c0[33]), fmaxf(c0[14 * 33], c0[15 * 33]));
            PO[pos * 33 + oc] = fmaxf(v + __ldg(&cb2[oc]), 0.f);
        }
        __syncthreads();
        // A3 fill: rows P*16+Q (P=1..7, Q=0..5), input 7x7 from PO
        for (int t = wid; t < 42; t += 8) {
            int P = t / 6 + 1, Q = t - (t / 6) * 6;
            int row = P * 16 + Q;
#pragma unroll
            for (int kw = 0; kw < 3; kw++) {
                int c = Q + kw - 1;
                float v = (c >= 0 && c < 7) ? PO[((P - 1) * 7 + c) * 33 + lane] : 0.f;
                uint32_t off = (uint32_t)(row * SAS + kw * 32 + lane) * 2;
                split_store(smem, SM_SAH + off, SM_SAL + off, v);
            }
        }
        __syncthreads();
        // conv3 mma: 24 units (m=1..6, n=0..3)
        for (int wt = wid; wt < 24; wt += 8) {
            int m = wt / 4 + 1, n = wt & 3;
            float acc[2][4];
#pragma unroll
            for (int bk = 0; bk < 2; bk++)
#pragma unroll
                for (int i = 0; i < 4; i++) acc[bk][i] = 0.f;
#pragma unroll
            for (int kh = 0; kh < 3; kh++) {
                int R0 = m * 16 + (kh - 1) * 16;
#pragma unroll
                for (int s = 0; s < 3; s++) {
                    uint32_t Abase = sb + ((s == 2) ? SM_SAL : SM_SAH);
                    uint32_t Bmat = sb + SM_SB + (uint32_t)(6 + kh * 2 + (s == 1 ? 1 : 0)) * SB_MAT;
#pragma unroll
                    for (int j = 0; j < 6; j++) {
                        uint32_t aaddr = Abase + (((uint32_t)R0 + a_r) * SAS + j * 16 + a_c) * 2;
                        uint32_t a0, a1, a2, a3;
                        ldsm4(a0, a1, a2, a3, aaddr);
                        uint32_t baddr = Bmat + ((n * 8 + b_r) * SAS + j * 16 + b_c) * 2;
                        uint32_t b0, b1;
                        ldsm2(b0, b1, baddr);
                        mma16816(acc[j & 1], a0, a1, a2, a3, b0, b1);
                    }
                }
            }
#pragma unroll
            for (int i = 0; i < 4; i++) acc[0][i] += acc[1][i];
            if (g < 6) {                               // Q = g valid; Q = g+8 never
                int pos6 = (m - 1) * 6 + g;
                int col = n * 8 + 2 * tg;
                C3[pos6 * 33 + col] = acc[0][0];
                C3[pos6 * 33 + col + 1] = acc[0][1];
            }
        }
        __syncthreads();
        // final: pool conv3 + bias + relu -> g_out3 + BN partials
        float* go = g_out3 + img * 288;
        {
            int oc = myoc, pos = tid - oc * 9;
            int pr = pos / 3, pc = pos - pr * 3;
            const float* c0 = C3 + ((2 * pr) * 6 + 2 * pc) * 33 + oc;
            float v = fmaxf(fmaxf(c0[0], c0[33]), fmaxf(c0[6 * 33], c0[7 * 33]));
            v = fmaxf(v + __ldg(&cb3[oc]), 0.f);
            go[tid] = v; lsum += v; lsq += v * v;
        }
        if (tid < 32) {
            int idx = tid + 256;
            int oc = myoc2, pos = idx - oc * 9;
            int pr = pos / 3, pc = pos - pr * 3;
            const float* c0 = C3 + ((2 * pr) * 6 + 2 * pc) * 33 + oc;
            float v = fmaxf(fmaxf(c0[0], c0[33]), fmaxf(c0[6 * 33], c0[7 * 33]));
            v = fmaxf(v + __ldg(&cb3[oc]), 0.f);
            go[idx] = v; lsum2 += v; lsq2 += v * v;
        }
    }
    __syncthreads();
    atomicAdd(&ssum[myoc], lsum); atomicAdd(&ssq[myoc], lsq);
    if (tid < 32) { atomicAdd(&ssum[myoc2], lsum2); atomicAdd(&ssq[myoc2], lsq2); }
    __syncthreads();
    if (tid < 32) {
        atomicAdd(&g_stats[tid], ssum[tid]);
        atomicAdd(&g_stats[32 + tid], ssq[tid]);
    }
}

// ---------------- BN finalize ---------------------------------------------------
__global__ void bn_finalize_kernel(const float* __restrict__ bn_g,
                                   const float* __restrict__ bn_b) {
    int c = threadIdx.x;
    if (c < 32) {
        const float inv_n = 1.0f / (float)(B * 9);
        float m = g_stats[c] * inv_n;
        float var = g_stats[32 + c] * inv_n - m * m;
        float sc = bn_g[c] * rsqrtf(var + 1e-5f);
        g_scale[c] = sc;
        g_shift[c] = bn_b[c] - m * sc;
    }
}

// ---------------- compose expert chain ------------------------------------------
__global__ void compose_kernel(const float* __restrict__ ew1, const float* __restrict__ eb1,
                               const float* __restrict__ ew2, const float* __restrict__ eb2,
                               const float* __restrict__ ew3, const float* __restrict__ eb3) {
    __shared__ float E3s[1280];
    __shared__ float C1s[1280];
    int a = blockIdx.x, tid = threadIdx.x;
    for (int i = tid; i < 1280; i += 128) E3s[i] = ew3[a * 1280 + i];
    __syncthreads();
    {
        float s[10];
#pragma unroll
        for (int o = 0; o < 10; o++) s[o] = 0.f;
        const float* e2r = ew2 + a * 16384 + tid * 128;
        for (int j = 0; j < 128; j++) {
            float e = e2r[j];
#pragma unroll
            for (int o = 0; o < 10; o++) s[o] += e * E3s[j * 10 + o];
        }
#pragma unroll
        for (int o = 0; o < 10; o++) C1s[tid * 10 + o] = s[o];
    }
    __syncthreads();
    if (tid < 10) {
        float bb = eb3[a * 10 + tid];
        for (int i = 0; i < 128; i++) {
            bb += eb2[a * 128 + i] * E3s[i * 10 + tid];
            bb += eb1[a * 128 + i] * C1s[i * 10 + tid];
        }
        g_bc[a * 10 + tid] = bb;
    }
    for (int k = tid; k < 288; k += 128) {
        float s[10];
#pragma unroll
        for (int o = 0; o < 10; o++) s[o] = 0.f;
        const float* e1r = ew1 + a * 36864 + k * 128;
        for (int i = 0; i < 128; i++) {
            float e = e1r[i];
#pragma unroll
            for (int o = 0; o < 10; o++) s[o] += e * C1s[i * 10 + o];
        }
#pragma unroll
        for (int o = 0; o < 10; o++) g_Wc[(a * 288 + k) * 10 + o] = s[o];
    }
}

// ---------------- MLP + argmax + composed selection -----------------------------
__global__ void __launch_bounds__(256) mlp_kernel(
    const float* __restrict__ pw1, const float* __restrict__ pb1,
    const float* __restrict__ pw2, const float* __restrict__ pb2,
    const float* __restrict__ pw3, const float* __restrict__ pb3,
    float* __restrict__ out, int write_actions) {
    __shared__ float ys[8 * 2 * 288];
    __shared__ float hA[8 * 2 * 128];
    __shared__ float hB[8 * 2 * 128];
    int w = threadIdx.x >> 5, lane = threadIdx.x & 31;
    float* yw = ys + w * 576;
    float* ha = hA + w * 256;
    float* hb = hB + w * 256;
    int e0 = blockIdx.x * 16 + w * 2;

    for (int idx = lane; idx < 576; idx += 32) {
        int e = idx / 288, k = idx - e * 288, c = k / 9;
        yw[idx] = g_out3[(e0 + e) * 288 + k] * g_scale[c] + g_shift[c];
    }
    __syncwarp();
    {
        float acc[2][4];
#pragma unroll
        for (int m = 0; m < 4; m++) {
            float bv = __ldg(&pb1[lane + 32 * m]);
            acc[0][m] = bv; acc[1][m] = bv;
        }
        for (int k = 0; k < 288; k++) {
            const float* wr = pw1 + k * 128 + lane;
            float w0 = wr[0], w1 = wr[32], w2 = wr[64], w3 = wr[96];
            float y0 = yw[k], y1 = yw[288 + k];
            acc[0][0] += y0 * w0; acc[0][1] += y0 * w1; acc[0][2] += y0 * w2; acc[0][3] += y0 * w3;
            acc[1][0] += y1 * w0; acc[1][1] += y1 * w1; acc[1][2] += y1 * w2; acc[1][3] += y1 * w3;
        }
#pragma unroll
        for (int e = 0; e < 2; e++)
#pragma unroll
            for (int m = 0; m < 4; m++)
                ha[e * 128 + lane + 32 * m] = fmaxf(acc[e][m], 0.f);
    }
    __syncwarp();
    {
        float acc[2][4];
#pragma unroll
        for (int m = 0; m < 4; m++) {
            float bv = __ldg(&pb2[lane + 32 * m]);
            acc[0][m] = bv; acc[1][m] = bv;
        }
        for (int k = 0; k < 128; k++) {
            const float* wr = pw2 + k * 128 + lane;
            float w0 = wr[0], w1 = wr[32], w2 = wr[64], w3 = wr[96];
            float y0 = ha[k], y1 = ha[128 + k];
            acc[0][0] += y0 * w0; acc[0][1] += y0 * w1; acc[0][2] += y0 * w2; acc[0][3] += y0 * w3;
            acc[1][0] += y1 * w0; acc[1][1] += y1 * w1; acc[1][2] += y1 * w2; acc[1][3] += y1 * w3;
        }
#pragma unroll
        for (int e = 0; e < 2; e++)
#pragma unroll
            for (int m = 0; m < 4; m++)
                hb[e * 128 + lane + 32 * m] = fmaxf(acc[e][m], 0.f);
    }
    __syncwarp();
    for (int e = 0; e < 2; e++) {
        float p0 = 0.f, p1 = 0.f, p2 = 0.f;
#pragma unroll
        for (int kk = 0; kk < 4; kk++) {
            int k = lane + 32 * kk;
            float hv = hb[e * 128 + k];
            const float* wr = pw3 + k * 3;
            p0 += hv * wr[0]; p1 += hv * wr[1]; p2 += hv * wr[2];
        }
#pragma unroll
        for (int off = 16; off > 0; off >>= 1) {
            p0 += __shfl_down_sync(0xffffffffu, p0, off);
            p1 += __shfl_down_sync(0xffffffffu, p1, off);
            p2 += __shfl_down_sync(0xffffffffu, p2, off);
        }
        int a = 0;
        if (lane == 0) {
            p0 += __ldg(&pb3[0]); p1 += __ldg(&pb3[1]); p2 += __ldg(&pb3[2]);
            float best = p0;
            if (p1 > best) { best = p1; a = 1; }
            if (p2 > best) { a = 2; }
        }
        a = __shfl_sync(0xffffffffu, a, 0);
        float po[10];
#pragma unroll
        for (int o = 0; o < 10; o++) po[o] = 0.f;
        const float* Wb = g_Wc + a * 2880;
        const float* ye = yw + e * 288;
#pragma unroll
        for (int kk = 0; kk < 9; kk++) {
            int k = lane + 32 * kk;
            float yv = ye[k];
            const float* wr = Wb + k * 10;
#pragma unroll
            for (int o = 0; o < 10; o++) po[o] += yv * wr[o];
        }
#pragma unroll
        for (int off = 16; off > 0; off >>= 1) {
#pragma unroll
            for (int o = 0; o < 10; o++) po[o] += __shfl_down_sync(0xffffffffu, po[o], off);
        }
        if (lane == 0) {
            int g = e0 + e;
#pragma unroll
            for (int o = 0; o < 10; o++) out[g * 10 + o] = po[o] + g_bc[a * 10 + o];
            if (write_actions) out[B * 10 + g] = (float)a;
        }
    }
}

// ---------------- launch --------------------------------------------------------
extern "C" void kernel_launch(void* const* d_in, const int* in_sizes, int n_in,
                              void* d_out, int out_size) {
    const float* x    = (const float*)d_in[0];
    const float* cw1  = (const float*)d_in[1];
    const float* cb1  = (const float*)d_in[2];
    const float* cw2  = (const float*)d_in[3];
    const float* cb2  = (const float*)d_in[4];
    const float* cw3  = (const float*)d_in[5];
    const float* cb3  = (const float*)d_in[6];
    const float* bn_g = (const float*)d_in[7];
    const float* bn_b = (const float*)d_in[8];
    const float* pw1  = (const float*)d_in[9];
    const float* pb1  = (const float*)d_in[10];
    const float* pw2  = (const float*)d_in[11];
    const float* pb2  = (const float*)d_in[12];
    const float* pw3  = (const float*)d_in[13];
    const float* pb3  = (const float*)d_in[14];
    const float* ew1  = (const float*)d_in[15];
    const float* eb1  = (const float*)d_in[16];
    const float* ew2  = (const float*)d_in[17];
    const float* eb2  = (const float*)d_in[18];
    const float* ew3  = (const float*)d_in[19];
    const float* eb3  = (const float*)d_in[20];
    float* out = (float*)d_out;
    int write_actions = (out_size >= B * 10 + B) ? 1 : 0;

    cudaFuncSetAttribute(conv23_kernel, cudaFuncAttributeMaxDynamicSharedMemorySize, SM_TOTAL);

    zero_stats_kernel<<<1, 64>>>();
    conv1_kernel<<<(B * 196) / 256, 256>>>(x, cw1, cb1);
    conv23_kernel<<<148, 256, SM_TOTAL>>>(cw2, cb2, cw3, cb3);
    bn_finalize_kernel<<<1, 32>>>(bn_g, bn_b);
    compose_kernel<<<3, 128>>>(ew1, eb1, ew2, eb2, ew3, eb3);
    mlp_kernel<<<B / 16, 256>>>(pw1, pb1, pw2, pb2, pw3, pb3, out, write_actions);
}

// round 5
// speedup vs baseline: 1.2969x; 1.2804x over previous
#include <cuda_runtime.h>
#include <cuda_bf16.h>
#include <cuda_fp16.h>
#include <cstdint>

#define B 4096

__device__ float g_out1[B * 6272];   // conv1 out, [b][pos][ic]
__device__ float g_out3[B * 288];    // conv3 out (pre-BN), [b][oc*9+pos]
__device__ float g_stats[64];
__device__ float g_scale[32], g_shift[32];
__device__ float g_Wc[3 * 288 * 10];
__device__ float g_bc[30];

// ---------------- portable tensor-core helpers (sm_80+ PTX only) ---------------
__device__ __forceinline__ uint32_t smem_u32(const void* p) {
    uint32_t a;
    asm("{ .reg .u64 t; cvta.to.shared.u64 t, %1; cvt.u32.u64 %0, t; }" : "=r"(a) : "l"(p));
    return a;
}
__device__ __forceinline__ void ldsm4(uint32_t& a0, uint32_t& a1, uint32_t& a2, uint32_t& a3, uint32_t addr) {
    asm volatile("ldmatrix.sync.aligned.m8n8.x4.shared.b16 {%0,%1,%2,%3}, [%4];"
                 : "=r"(a0), "=r"(a1), "=r"(a2), "=r"(a3) : "r"(addr));
}
__device__ __forceinline__ void mma16816(float* c, uint32_t a0, uint32_t a1, uint32_t a2, uint32_t a3,
                                         uint32_t b0, uint32_t b1) {
    asm volatile("mma.sync.aligned.m16n8k16.row.col.f32.f16.f16.f32 "
                 "{%0,%1,%2,%3}, {%4,%5,%6,%7}, {%8,%9}, {%0,%1,%2,%3};"
                 : "+f"(c[0]), "+f"(c[1]), "+f"(c[2]), "+f"(c[3])
                 : "r"(a0), "r"(a1), "r"(a2), "r"(a3), "r"(b0), "r"(b1));
}
__device__ __forceinline__ void split_store(char* smem, uint32_t oh, uint32_t ol, float v) {
    __half h = __float2half_rn(v);
    __half l = __float2half_rn(v - __half2float(h));
    *(__half*)(smem + oh) = h;
    *(__half*)(smem + ol) = l;
}

__global__ void zero_stats_kernel() { if (threadIdx.x < 64) g_stats[threadIdx.x] = 0.f; }

// ---------------- conv1 (1->32)+relu+pool -> [b][pos][ic] -----------------------
__global__ void conv1_kernel(const float* __restrict__ x,
                             const float* __restrict__ cw1,
                             const float* __restrict__ cb1) {
    __shared__ float w1s[288], b1s[32];
    int tid = threadIdx.x;
    for (int i = tid; i < 288; i += 256) w1s[i] = cw1[i];
    if (tid < 32) b1s[tid] = cb1[tid];
    __syncthreads();
    int idx = blockIdx.x * 256 + tid;
    int b = idx / 196, pos = idx - b * 196;
    int ph = pos / 14, pw = pos - ph * 14;
    float p[4][4];
    const float* xb = x + b * 784;
#pragma unroll
    for (int r = 0; r < 4; r++) {
        int ir = 2 * ph - 1 + r;
#pragma unroll
        for (int c = 0; c < 4; c++) {
            int ic = 2 * pw - 1 + c;
            p[r][c] = (ir >= 0 && ir < 28 && ic >= 0 && ic < 28) ? xb[ir * 28 + ic] : 0.f;
        }
    }
    float vals[32];
#pragma unroll 4
    for (int oc = 0; oc < 32; oc++) {
        float a0 = 0.f, a1 = 0.f, a2 = 0.f, a3 = 0.f;
#pragma unroll
        for (int kh = 0; kh < 3; kh++)
#pragma unroll
            for (int kw = 0; kw < 3; kw++) {
                float w = w1s[oc * 9 + kh * 3 + kw];
                a0 += p[kh][kw] * w;     a1 += p[kh][kw + 1] * w;
                a2 += p[kh + 1][kw] * w; a3 += p[kh + 1][kw + 1] * w;
            }
        vals[oc] = fmaxf(fmaxf(fmaxf(a0, a1), fmaxf(a2, a3)) + b1s[oc], 0.f);
    }
    float4* dst4 = (float4*)(g_out1 + b * 6272 + pos * 32);
#pragma unroll
    for (int j = 0; j < 8; j++)
        dst4[j] = make_float4(vals[4 * j], vals[4 * j + 1], vals[4 * j + 2], vals[4 * j + 3]);
}

// ---------------- fused conv2+conv3 via mma.sync, K=32 tap scheme ---------------
// A: 256 storage rows (s = logical+1) x 40 halfs; hi + lo.  K = ic only.
// tap (kh,kw) = row offset (kh-1)*16 + (kw-1).
#define SAS 40
#define SM_AH 1024
#define SM_AL (SM_AH + 20480)                  // 21504
#define SM_B  (SM_AL + 20480)                  // 41984
#define SB_MAT 2560                            // 32 oc x 40 k halfs
#define SM_C2 (SM_B + 36 * SB_MAT)             // 134144
#define SM_PO (SM_C2 + 25872)                  // 160016
#define SM_C3 (SM_PO + 6468)                   // 166484
#define SM_TOTAL (SM_C3 + 4752 + 44)           // 171280

__global__ void __launch_bounds__(256, 1) conv23_kernel(
    const float* __restrict__ cw2, const float* __restrict__ cb2,
    const float* __restrict__ cw3, const float* __restrict__ cb3) {
    extern __shared__ char smem[];
    uint32_t sb = smem_u32(smem);
    int tid = threadIdx.x, wid = tid >> 5, lane = tid & 31;
    float* ssum = (float*)(smem + 64);
    float* ssq  = (float*)(smem + 192);
    float* C2 = (float*)(smem + SM_C2);
    float* PO = (float*)(smem + SM_PO);
    float* C3 = (float*)(smem + SM_C3);

    if (tid < 32) { ssum[tid] = 0.f; ssq[tid] = 0.f; }
    // zero A+B region once (133120 B = 8320 float4)
    for (int i = tid; i < 8320; i += 256)
        ((float4*)(smem + SM_AH))[i] = make_float4(0.f, 0.f, 0.f, 0.f);
    __syncthreads();
    // B fill: [conv][tap][split][oc][ic]
    for (int idx = tid; idx < 18432; idx += 256) {
        int conv = idx / 9216, r = idx % 9216;
        int tap = r / 1024, r2 = r % 1024;
        int oc = r2 >> 5, ic = r2 & 31;
        int kh = tap / 3, kw = tap % 3;
        float w = __ldg(&(conv ? cw3 : cw2)[oc * 288 + ic * 9 + kh * 3 + kw]);
        uint32_t bh = SM_B + (uint32_t)((conv * 9 + tap) * 2) * SB_MAT + (oc * SAS + ic) * 2;
        split_store(smem, bh, bh + SB_MAT, w);
    }
    __syncthreads();

    int g = lane >> 2, tg = lane & 3;
    uint32_t a_r = (uint32_t)(lane & 15), a_c = (uint32_t)((lane >> 4) * 8);
    uint32_t b_row = (uint32_t)(((lane >> 4) << 3) + (lane & 7));   // within 16-row n-pair
    uint32_t b_c = (uint32_t)((lane & 8) ? 8 : 0);
    float lsum = 0.f, lsq = 0.f, lsum2 = 0.f, lsq2 = 0.f;
    int myoc = tid / 9, myoc2 = (tid + 256) / 9;

    for (int it = 0; it < 28; it++) {
        int img = blockIdx.x + 148 * it;
        if (img >= B) break;
        __syncthreads();   // A free of prior readers
        // A2 fill: t = (P-1)*14+Q exactly; s = P*16+Q+1
        const float* gin = g_out1 + img * 6272;
        for (int t = wid; t < 196; t += 8) {
            int P = t / 14 + 1, Q = t - (t / 14) * 14;
            float v = gin[t * 32 + lane];
            uint32_t off = (uint32_t)((P * 16 + Q + 1) * SAS + lane) * 2;
            split_store(smem, SM_AH + off, SM_AL + off, v);
        }
        __syncthreads();
        // conv2 mma: m-tiles 1..14, N=32 (2 n-pairs)
        for (int m = 1 + wid; m <= 14; m += 8) {
            float acc[2][4][4];
#pragma unroll
            for (int bk = 0; bk < 2; bk++)
#pragma unroll
                for (int n = 0; n < 4; n++)
#pragma unroll
                    for (int i = 0; i < 4; i++) acc[bk][n][i] = 0.f;
#pragma unroll
            for (int tap = 0; tap < 9; tap++) {
                int R0s = m * 16 + (tap / 3 - 1) * 16 + (tap % 3 - 1) + 1;
                uint32_t bmat = sb + SM_B + (uint32_t)(tap * 2) * SB_MAT;
#pragma unroll
                for (int j = 0; j < 2; j++) {
                    uint32_t aoff = (uint32_t)(((uint32_t)R0s + a_r) * SAS + j * 16 + a_c) * 2;
                    uint32_t ah0, ah1, ah2, ah3, al0, al1, al2, al3;
                    ldsm4(ah0, ah1, ah2, ah3, sb + SM_AH + aoff);
                    ldsm4(al0, al1, al2, al3, sb + SM_AL + aoff);
#pragma unroll
                    for (int np = 0; np < 2; np++) {
                        uint32_t boff = ((np * 16 + b_row) * SAS + (uint32_t)j * 16 + b_c) * 2;
                        uint32_t bh0, bh1, bh2, bh3, bl0, bl1, bl2, bl3;
                        ldsm4(bh0, bh1, bh2, bh3, bmat + boff);
                        ldsm4(bl0, bl1, bl2, bl3, bmat + SB_MAT + boff);
                        int n0 = np * 2, n1 = np * 2 + 1;
                        mma16816(acc[j][n0], ah0, ah1, ah2, ah3, bh0, bh1);
                        mma16816(acc[j][n1], ah0, ah1, ah2, ah3, bh2, bh3);
                        mma16816(acc[j ^ 1][n0], ah0, ah1, ah2, ah3, bl0, bl1);
                        mma16816(acc[j ^ 1][n1], ah0, ah1, ah2, ah3, bl2, bl3);
                        mma16816(acc[j][n0], al0, al1, al2, al3, bh0, bh1);
                        mma16816(acc[j][n1], al0, al1, al2, al3, bh2, bh3);
                    }
                }
            }
#pragma unroll
            for (int n = 0; n < 4; n++) {
#pragma unroll
                for (int i = 0; i < 4; i++) acc[0][n][i] += acc[1][n][i];
                int col = n * 8 + 2 * tg;
                int pos = (m - 1) * 14 + g;
                C2[pos * 33 + col] = acc[0][n][0];
                C2[pos * 33 + col + 1] = acc[0][n][1];
                if (g < 6) {
                    int pos2 = pos + 8;
                    C2[pos2 * 33 + col] = acc[0][n][2];
                    C2[pos2 * 33 + col + 1] = acc[0][n][3];
                }
            }
        }
        __syncthreads();
        // pool conv2 -> PO (bias+relu)
        for (int idx = tid; idx < 1568; idx += 256) {
            int oc = idx & 31, pos = idx >> 5;
            int pr = pos / 7, pc = pos - pr * 7;
            const float* c0 = C2 + ((2 * pr) * 14 + 2 * pc) * 33 + oc;
            float v = fmaxf(fmaxf(c0[0], c0[33]), fmaxf(c0[14 * 33], c0[15 * 33]));
            PO[pos * 33 + oc] = fmaxf(v + __ldg(&cb2[oc]), 0.f);
        }
        __syncthreads();
        // A3 fill: input 7x7 from PO; s = P*16+Q+1, P=1..7, Q=0..6
        for (int t = wid; t < 49; t += 8) {
            int P = t / 7 + 1, Q = t - (t / 7) * 7;
            float v = PO[t * 33 + lane];
            uint32_t off = (uint32_t)((P * 16 + Q + 1) * SAS + lane) * 2;
            split_store(smem, SM_AH + off, SM_AL + off, v);
        }
        __syncthreads();
        // conv3 mma: 12 units (m=1..6 x npair)
        for (int u = wid; u < 12; u += 8) {
            int m = u >> 1, np = u & 1;
            m += 1;
            float acc[2][2][4];
#pragma unroll
            for (int bk = 0; bk < 2; bk++)
#pragma unroll
                for (int n = 0; n < 2; n++)
#pragma unroll
                    for (int i = 0; i < 4; i++) acc[bk][n][i] = 0.f;
#pragma unroll
            for (int tap = 0; tap < 9; tap++) {
                int R0s = m * 16 + (tap / 3 - 1) * 16 + (tap % 3 - 1) + 1;
                uint32_t bmat = sb + SM_B + (uint32_t)((9 + tap) * 2) * SB_MAT;
#pragma unroll
                for (int j = 0; j < 2; j++) {
                    uint32_t aoff = (uint32_t)(((uint32_t)R0s + a_r) * SAS + j * 16 + a_c) * 2;
                    uint32_t ah0, ah1, ah2, ah3, al0, al1, al2, al3;
                    ldsm4(ah0, ah1, ah2, ah3, sb + SM_AH + aoff);
                    ldsm4(al0, al1, al2, al3, sb + SM_AL + aoff);
                    uint32_t boff = ((np * 16 + b_row) * SAS + (uint32_t)j * 16 + b_c) * 2;
                    uint32_t bh0, bh1, bh2, bh3, bl0, bl1, bl2, bl3;
                    ldsm4(bh0, bh1, bh2, bh3, bmat + boff);
                    ldsm4(bl0, bl1, bl2, bl3, bmat + SB_MAT + boff);
                    mma16816(acc[j][0], ah0, ah1, ah2, ah3, bh0, bh1);
                    mma16816(acc[j][1], ah0, ah1, ah2, ah3, bh2, bh3);
                    mma16816(acc[j ^ 1][0], ah0, ah1, ah2, ah3, bl0, bl1);
                    mma16816(acc[j ^ 1][1], ah0, ah1, ah2, ah3, bl2, bl3);
                    mma16816(acc[j][0], al0, al1, al2, al3, bh0, bh1);
                    mma16816(acc[j][1], al0, al1, al2, al3, bh2, bh3);
                }
            }
            if (g < 6) {
                int pos6 = (m - 1) * 6 + g;
#pragma unroll
                for (int n = 0; n < 2; n++) {
                    int col = np * 16 + n * 8 + 2 * tg;
                    C3[pos6 * 33 + col] = acc[0][n][0] + acc[1][n][0];
                    C3[pos6 * 33 + col + 1] = acc[0][n][1] + acc[1][n][1];
                }
            }
        }
        __syncthreads();
        // final: pool conv3 + bias + relu -> g_out3 + BN partials
        float* go = g_out3 + img * 288;
        {
            int oc = myoc, pos = tid - oc * 9;
            int pr = pos / 3, pc = pos - pr * 3;
            const float* c0 = C3 + ((2 * pr) * 6 + 2 * pc) * 33 + oc;
            float v = fmaxf(fmaxf(c0[0], c0[33]), fmaxf(c0[6 * 33], c0[7 * 33]));
            v = fmaxf(v + __ldg(&cb3[oc]), 0.f);
            go[tid] = v; lsum += v; lsq += v * v;
        }
        if (tid < 32) {
            int idx = tid + 256;
            int oc = myoc2, pos = idx - oc * 9;
            int pr = pos / 3, pc = pos - pr * 3;
            const float* c0 = C3 + ((2 * pr) * 6 + 2 * pc) * 33 + oc;
            float v = fmaxf(fmaxf(c0[0], c0[33]), fmaxf(c0[6 * 33], c0[7 * 33]));
            v = fmaxf(v + __ldg(&cb3[oc]), 0.f);
            go[idx] = v; lsum2 += v; lsq2 += v * v;
        }
    }
    __syncthreads();
    atomicAdd(&ssum[myoc], lsum); atomicAdd(&ssq[myoc], lsq);
    if (tid < 32) { atomicAdd(&ssum[myoc2], lsum2); atomicAdd(&ssq[myoc2], lsq2); }
    __syncthreads();
    if (tid < 32) {
        atomicAdd(&g_stats[tid], ssum[tid]);
        atomicAdd(&g_stats[32 + tid], ssq[tid]);
    }
}

// ---------------- BN finalize ---------------------------------------------------
__global__ void bn_finalize_kernel(const float* __restrict__ bn_g,
                                   const float* __restrict__ bn_b) {
    int c = threadIdx.x;
    if (c < 32) {
        const float inv_n = 1.0f / (float)(B * 9);
        float m = g_stats[c] * inv_n;
        float var = g_stats[32 + c] * inv_n - m * m;
        float sc = bn_g[c] * rsqrtf(var + 1e-5f);
        g_scale[c] = sc;
        g_shift[c] = bn_b[c] - m * sc;
    }
}

// ---------------- compose expert chain ------------------------------------------
__global__ void compose_kernel(const float* __restrict__ ew1, const float* __restrict__ eb1,
                               const float* __restrict__ ew2, const float* __restrict__ eb2,
                               const float* __restrict__ ew3, const float* __restrict__ eb3) {
    __shared__ float E3s[1280];
    __shared__ float C1s[1280];
    int a = blockIdx.x, tid = threadIdx.x;
    for (int i = tid; i < 1280; i += 128) E3s[i] = ew3[a * 1280 + i];
    __syncthreads();
    {
        float s[10];
#pragma unroll
        for (int o = 0; o < 10; o++) s[o] = 0.f;
        const float* e2r = ew2 + a * 16384 + tid * 128;
        for (int j = 0; j < 128; j++) {
            float e = e2r[j];
#pragma unroll
            for (int o = 0; o < 10; o++) s[o] += e * E3s[j * 10 + o];
        }
#pragma unroll
        for (int o = 0; o < 10; o++) C1s[tid * 10 + o] = s[o];
    }
    __syncthreads();
    if (tid < 10) {
        float bb = eb3[a * 10 + tid];
        for (int i = 0; i < 128; i++) {
            bb += eb2[a * 128 + i] * E3s[i * 10 + tid];
            bb += eb1[a * 128 + i] * C1s[i * 10 + tid];
        }
        g_bc[a * 10 + tid] = bb;
    }
    for (int k = tid; k < 288; k += 128) {
        float s[10];
#pragma unroll
        for (int o = 0; o < 10; o++) s[o] = 0.f;
        const float* e1r = ew1 + a * 36864 + k * 128;
        for (int i = 0; i < 128; i++) {
            float e = e1r[i];
#pragma unroll
            for (int o = 0; o < 10; o++) s[o] += e * C1s[i * 10 + o];
        }
#pragma unroll
        for (int o = 0; o < 10; o++) g_Wc[(a * 288 + k) * 10 + o] = s[o];
    }
}

// ---------------- MLP + argmax + composed selection -----------------------------
__global__ void __launch_bounds__(256) mlp_kernel(
    const float* __restrict__ pw1, const float* __restrict__ pb1,
    const float* __restrict__ pw2, const float* __restrict__ pb2,
    const float* __restrict__ pw3, const float* __restrict__ pb3,
    float* __restrict__ out, int write_actions) {
    __shared__ float ys[8 * 2 * 288];
    __shared__ float hA[8 * 2 * 128];
    __shared__ float hB[8 * 2 * 128];
    int w = threadIdx.x >> 5, lane = threadIdx.x & 31;
    float* yw = ys + w * 576;
    float* ha = hA + w * 256;
    float* hb = hB + w * 256;
    int e0 = blockIdx.x * 16 + w * 2;

    for (int idx = lane; idx < 576; idx += 32) {
        int e = idx / 288, k = idx - e * 288, c = k / 9;
        yw[idx] = g_out3[(e0 + e) * 288 + k] * g_scale[c] + g_shift[c];
    }
    __syncwarp();
    {
        float acc[2][4];
#pragma unroll
        for (int m = 0; m < 4; m++) {
            float bv = __ldg(&pb1[lane + 32 * m]);
            acc[0][m] = bv; acc[1][m] = bv;
        }
        for (int k = 0; k < 288; k++) {
            const float* wr = pw1 + k * 128 + lane;
            float w0 = wr[0], w1 = wr[32], w2 = wr[64], w3 = wr[96];
            float y0 = yw[k], y1 = yw[288 + k];
            acc[0][0] += y0 * w0; acc[0][1] += y0 * w1; acc[0][2] += y0 * w2; acc[0][3] += y0 * w3;
            acc[1][0] += y1 * w0; acc[1][1] += y1 * w1; acc[1][2] += y1 * w2; acc[1][3] += y1 * w3;
        }
#pragma unroll
        for (int e = 0; e < 2; e++)
#pragma unroll
            for (int m = 0; m < 4; m++)
                ha[e * 128 + lane + 32 * m] = fmaxf(acc[e][m], 0.f);
    }
    __syncwarp();
    {
        float acc[2][4];
#pragma unroll
        for (int m = 0; m < 4; m++) {
            float bv = __ldg(&pb2[lane + 32 * m]);
            acc[0][m] = bv; acc[1][m] = bv;
        }
        for (int k = 0; k < 128; k++) {
            const float* wr = pw2 + k * 128 + lane;
            float w0 = wr[0], w1 = wr[32], w2 = wr[64], w3 = wr[96];
            float y0 = ha[k], y1 = ha[128 + k];
            acc[0][0] += y0 * w0; acc[0][1] += y0 * w1; acc[0][2] += y0 * w2; acc[0][3] += y0 * w3;
            acc[1][0] += y1 * w0; acc[1][1] += y1 * w1; acc[1][2] += y1 * w2; acc[1][3] += y1 * w3;
        }
#pragma unroll
        for (int e = 0; e < 2; e++)
#pragma unroll
            for (int m = 0; m < 4; m++)
                hb[e * 128 + lane + 32 * m] = fmaxf(acc[e][m], 0.f);
    }
    __syncwarp();
    for (int e = 0; e < 2; e++) {
        float p0 = 0.f, p1 = 0.f, p2 = 0.f;
#pragma unroll
        for (int kk = 0; kk < 4; kk++) {
            int k = lane + 32 * kk;
            float hv = hb[e * 128 + k];
            const float* wr = pw3 + k * 3;
            p0 += hv * wr[0]; p1 += hv * wr[1]; p2 += hv * wr[2];
        }
#pragma unroll
        for (int off = 16; off > 0; off >>= 1) {
            p0 += __shfl_down_sync(0xffffffffu, p0, off);
            p1 += __shfl_down_sync(0xffffffffu, p1, off);
            p2 += __shfl_down_sync(0xffffffffu, p2, off);
        }
        int a = 0;
        if (lane == 0) {
            p0 += __ldg(&pb3[0]); p1 += __ldg(&pb3[1]); p2 += __ldg(&pb3[2]);
            float best = p0;
            if (p1 > best) { best = p1; a = 1; }
            if (p2 > best) { a = 2; }
        }
        a = __shfl_sync(0xffffffffu, a, 0);
        float po[10];
#pragma unroll
        for (int o = 0; o < 10; o++) po[o] = 0.f;
        const float* Wb = g_Wc + a * 2880;
        const float* ye = yw + e * 288;
#pragma unroll
        for (int kk = 0; kk < 9; kk++) {
            int k = lane + 32 * kk;
            float yv = ye[k];
            const float* wr = Wb + k * 10;
#pragma unroll
            for (int o = 0; o < 10; o++) po[o] += yv * wr[o];
        }
#pragma unroll
        for (int off = 16; off > 0; off >>= 1) {
#pragma unroll
            for (int o = 0; o < 10; o++) po[o] += __shfl_down_sync(0xffffffffu, po[o], off);
        }
        if (lane == 0) {
            int g = e0 + e;
#pragma unroll
            for (int o = 0; o < 10; o++) out[g * 10 + o] = po[o] + g_bc[a * 10 + o];
            if (write_actions) out[B * 10 + g] = (float)a;
        }
    }
}

// ---------------- launch --------------------------------------------------------
extern "C" void kernel_launch(void* const* d_in, const int* in_sizes, int n_in,
                              void* d_out, int out_size) {
    const float* x    = (const float*)d_in[0];
    const float* cw1  = (const float*)d_in[1];
    const float* cb1  = (const float*)d_in[2];
    const float* cw2  = (const float*)d_in[3];
    const float* cb2  = (const float*)d_in[4];
    const float* cw3  = (const float*)d_in[5];
    const float* cb3  = (const float*)d_in[6];
    const float* bn_g = (const float*)d_in[7];
    const float* bn_b = (const float*)d_in[8];
    const float* pw1  = (const float*)d_in[9];
    const float* pb1  = (const float*)d_in[10];
    const float* pw2  = (const float*)d_in[11];
    const float* pb2  = (const float*)d_in[12];
    const float* pw3  = (const float*)d_in[13];
    const float* pb3  = (const float*)d_in[14];
    const float* ew1  = (const float*)d_in[15];
    const float* eb1  = (const float*)d_in[16];
    const float* ew2  = (const float*)d_in[17];
    const float* eb2  = (const float*)d_in[18];
    const float* ew3  = (const float*)d_in[19];
    const float* eb3  = (const float*)d_in[20];
    float* out = (float*)d_out;
    int write_actions = (out_size >= B * 10 + B) ? 1 : 0;

    cudaFuncSetAttribute(conv23_kernel, cudaFuncAttributeMaxDynamicSharedMemorySize, SM_TOTAL);

    zero_stats_kernel<<<1, 64>>>();
    conv1_kernel<<<(B * 196) / 256, 256>>>(x, cw1, cb1);
    conv23_kernel<<<148, 256, SM_TOTAL>>>(cw2, cb2, cw3, cb3);
    bn_finalize_kernel<<<1, 32>>>(bn_g, bn_b);
    compose_kernel<<<3, 128>>>(ew1, eb1, ew2, eb2, ew3, eb3);
    mlp_kernel<<<B / 16, 256>>>(pw1, pb1, pw2, pb2, pw3, pb3, out, write_actions);
}

// round 6
// speedup vs baseline: 1.3177x; 1.0161x over previous
#include <cuda_runtime.h>
#include <cuda_bf16.h>
#include <cuda_fp16.h>
#include <cstdint>

#define B 4096

__device__ float g_out1[B * 6272];   // conv1 out, [b][pos][ic]
__device__ float g_out3[B * 288];    // conv3 out (pre-BN), [b][oc*9+pos]
__device__ float g_stats[64];
__device__ float g_scale[32], g_shift[32];
__device__ float g_Wc[3 * 288 * 10];
__device__ float g_bc[30];

// ---------------- portable tensor-core helpers (sm_80+ PTX only) ---------------
__device__ __forceinline__ uint32_t smem_u32(const void* p) {
    uint32_t a;
    asm("{ .reg .u64 t; cvta.to.shared.u64 t, %1; cvt.u32.u64 %0, t; }" : "=r"(a) : "l"(p));
    return a;
}
#define LDSM4(r, addr) \
    asm volatile("ldmatrix.sync.aligned.m8n8.x4.shared.b16 {%0,%1,%2,%3}, [%4];" \
                 : "=r"((r)[0]), "=r"((r)[1]), "=r"((r)[2]), "=r"((r)[3]) : "r"(addr))
__device__ __forceinline__ void mma16816(float* c, const uint32_t a[4], uint32_t b0, uint32_t b1) {
    asm volatile("mma.sync.aligned.m16n8k16.row.col.f32.f16.f16.f32 "
                 "{%0,%1,%2,%3}, {%4,%5,%6,%7}, {%8,%9}, {%0,%1,%2,%3};"
                 : "+f"(c[0]), "+f"(c[1]), "+f"(c[2]), "+f"(c[3])
                 : "r"(a[0]), "r"(a[1]), "r"(a[2]), "r"(a[3]), "r"(b0), "r"(b1));
}
__device__ __forceinline__ void mma_pair(float* c0, float* c1, const uint32_t a[4], const uint32_t b[4]) {
    mma16816(c0, a, b[0], b[1]);
    mma16816(c1, a, b[2], b[3]);
}
__device__ __forceinline__ void split_store(char* smem, uint32_t oh, uint32_t ol, float v) {
    __half h = __float2half_rn(v);
    __half l = __float2half_rn(v - __half2float(h));
    *(__half*)(smem + oh) = h;
    *(__half*)(smem + ol) = l;
}

__global__ void zero_stats_kernel() { if (threadIdx.x < 64) g_stats[threadIdx.x] = 0.f; }

// ---------------- conv1 (1->32)+relu+pool -> [b][pos][ic] -----------------------
__global__ void conv1_kernel(const float* __restrict__ x,
                             const float* __restrict__ cw1,
                             const float* __restrict__ cb1) {
    __shared__ float w1s[288], b1s[32];
    int tid = threadIdx.x;
    for (int i = tid; i < 288; i += 256) w1s[i] = cw1[i];
    if (tid < 32) b1s[tid] = cb1[tid];
    __syncthreads();
    int idx = blockIdx.x * 256 + tid;
    int b = idx / 196, pos = idx - b * 196;
    int ph = pos / 14, pw = pos - ph * 14;
    float p[4][4];
    const float* xb = x + b * 784;
#pragma unroll
    for (int r = 0; r < 4; r++) {
        int ir = 2 * ph - 1 + r;
#pragma unroll
        for (int c = 0; c < 4; c++) {
            int ic = 2 * pw - 1 + c;
            p[r][c] = (ir >= 0 && ir < 28 && ic >= 0 && ic < 28) ? xb[ir * 28 + ic] : 0.f;
        }
    }
    float vals[32];
#pragma unroll 4
    for (int oc = 0; oc < 32; oc++) {
        float a0 = 0.f, a1 = 0.f, a2 = 0.f, a3 = 0.f;
#pragma unroll
        for (int kh = 0; kh < 3; kh++)
#pragma unroll
            for (int kw = 0; kw < 3; kw++) {
                float w = w1s[oc * 9 + kh * 3 + kw];
                a0 += p[kh][kw] * w;     a1 += p[kh][kw + 1] * w;
                a2 += p[kh + 1][kw] * w; a3 += p[kh + 1][kw + 1] * w;
            }
        vals[oc] = fmaxf(fmaxf(fmaxf(a0, a1), fmaxf(a2, a3)) + b1s[oc], 0.f);
    }
    float4* dst4 = (float4*)(g_out1 + b * 6272 + pos * 32);
#pragma unroll
    for (int j = 0; j < 8; j++)
        dst4[j] = make_float4(vals[4 * j], vals[4 * j + 1], vals[4 * j + 2], vals[4 * j + 3]);
}

// ---------------- fused conv2+conv3, 2 images/iter, B-hoisted mma ---------------
#define SAS 40
#define SM_A2 1024                        // 4 x 20480 (img0 hi, img0 lo, img1 hi, img1 lo)
#define SM_A3 82944                       // 4 x 10880 (136 rows)
#define SM_B  126464                      // 36 x 2560
#define SB_MAT 2560
#define SM_C2 1024                        // 2 x 25872 (aliases A2, used after A2 dead)
#define SM_PO 52768                       // 2 x 6468
#define SM_C3 65704                       // 2 x 4752
#define SM_TOTAL 218624

__global__ void __launch_bounds__(256, 1) conv23_kernel(
    const float* __restrict__ cw2, const float* __restrict__ cb2,
    const float* __restrict__ cw3, const float* __restrict__ cb3) {
    extern __shared__ char smem[];
    uint32_t sb = smem_u32(smem);
    int tid = threadIdx.x, wid = tid >> 5, lane = tid & 31;
    float* ssum = (float*)(smem + 64);
    float* ssq  = (float*)(smem + 192);

    if (tid < 32) { ssum[tid] = 0.f; ssq[tid] = 0.f; }
    // zero A2 + A3 regions once
    for (int i = tid; i < 7840; i += 256)
        ((float4*)(smem + SM_A2))[i] = make_float4(0.f, 0.f, 0.f, 0.f);
    __syncthreads();
    // B fill: [conv][tap][split][oc][ic]
    for (int idx = tid; idx < 18432; idx += 256) {
        int conv = idx / 9216, r = idx % 9216;
        int tap = r / 1024, r2 = r % 1024;
        int oc = r2 >> 5, ic = r2 & 31;
        int kh = tap / 3, kw = tap % 3;
        float w = __ldg(&(conv ? cw3 : cw2)[oc * 288 + ic * 9 + kh * 3 + kw]);
        uint32_t bh = SM_B + (uint32_t)((conv * 9 + tap) * 2) * SB_MAT + (oc * SAS + ic) * 2;
        split_store(smem, bh, bh + SB_MAT, w);
    }
    __syncthreads();

    int g = lane >> 2, tg = lane & 3;
    uint32_t a_r = (uint32_t)(lane & 15), a_c = (uint32_t)((lane >> 4) * 8);
    uint32_t b_row = (uint32_t)(((lane >> 4) << 3) + (lane & 7));
    uint32_t b_c = (uint32_t)((lane & 8) ? 8 : 0);
    float lsum = 0.f, lsq = 0.f, lsum2 = 0.f, lsq2 = 0.f;
    int myoc = tid / 9, myoc2 = (tid + 256) / 9;

    // conv2 tile assignment (4 per warp, last invalid for wid>=4)
    int mt[4], pim[4], val2[4];
    uint32_t abh[4], abl[4];
#pragma unroll
    for (int t = 0; t < 4; t++) {
        int wt = wid + 8 * t;
        val2[t] = wt < 28;
        int p = val2[t] ? wt / 14 : 0;
        mt[t] = val2[t] ? wt % 14 + 1 : 1;
        pim[t] = p;
        abh[t] = sb + SM_A2 + (uint32_t)p * 40960u;
        abl[t] = abh[t] + 20480u;
    }
    // conv3 unit assignment (exactly 3 per warp)
    int np3 = wid & 1;
    int p3[3], mu[3];
#pragma unroll
    for (int t = 0; t < 3; t++) {
        int u = wid + 8 * t;
        p3[t] = u / 12;
        mu[t] = ((u % 12) >> 1) + 1;
    }

    for (int it = 0; it < 14; it++) {
        int img0 = blockIdx.x + 296 * it;
        __syncthreads();                                    // S1
        // ---- A2 fill (2 images) + padding re-zero ----
        for (int t = wid; t < 392; t += 8) {
            int p = t >= 196, tt = t - (p ? 196 : 0);
            int img = img0 + p * 148;
            int P = tt / 14 + 1, Q = tt - (tt / 14) * 14;
            float v = (img < B) ? g_out1[img * 6272 + tt * 32 + lane] : 0.f;
            uint32_t off = (uint32_t)((P * 16 + Q + 1) * SAS + lane) * 2;
            uint32_t hb = SM_A2 + (uint32_t)p * 40960u;
            split_store(smem, hb + off, hb + 20480u + off, v);
        }
        for (int z = tid; z < 1200; z += 256) {
            int si = z / 300, r = z - si * 300;
            int ri = r / 5, q = r - ri * 5;
            int row;
            if (ri < 17) row = ri;
            else if (ri < 45) { int k = ri - 17; row = (k >> 1) * 16 + 31 + (k & 1); }
            else row = 241 + (ri - 45);
            *(float4*)(smem + SM_A2 + si * 20480 + row * 80 + q * 16) =
                make_float4(0.f, 0.f, 0.f, 0.f);
        }
        __syncthreads();                                    // S2
        // ---- conv2 mma (B hoisted per tap) ----
        float acc[4][4][4];
#pragma unroll
        for (int t = 0; t < 4; t++)
#pragma unroll
            for (int n = 0; n < 4; n++)
#pragma unroll
                for (int i = 0; i < 4; i++) acc[t][n][i] = 0.f;
#pragma unroll
        for (int tap = 0; tap < 9; tap++) {
            uint32_t bmat = sb + SM_B + (uint32_t)(tap * 2) * SB_MAT;
            uint32_t Bh[2][2][4], Bl[2][2][4];
#pragma unroll
            for (int np = 0; np < 2; np++)
#pragma unroll
                for (int j = 0; j < 2; j++) {
                    uint32_t boff = (((uint32_t)np * 16 + b_row) * SAS + (uint32_t)j * 16 + b_c) * 2;
                    LDSM4(Bh[np][j], bmat + boff);
                    LDSM4(Bl[np][j], bmat + SB_MAT + boff);
                }
            int dr = (tap / 3 - 1) * 16 + (tap % 3 - 1) + 1;
#pragma unroll
            for (int j = 0; j < 2; j++) {
                uint32_t Ah[4][4], Al[4][4];
#pragma unroll
                for (int t = 0; t < 4; t++) {
                    uint32_t aoff = (uint32_t)((mt[t] * 16 + dr + (int)a_r) * SAS) * 2
                                    + ((uint32_t)j * 16 + a_c) * 2;
                    LDSM4(Ah[t], abh[t] + aoff);
                    LDSM4(Al[t], abl[t] + aoff);
                }
#pragma unroll
                for (int t = 0; t < 4; t++) if (val2[t]) {
                    mma_pair(acc[t][0], acc[t][1], Ah[t], Bh[0][j]);
                    mma_pair(acc[t][2], acc[t][3], Ah[t], Bh[1][j]);
                }
#pragma unroll
                for (int t = 0; t < 4; t++) if (val2[t]) {
                    mma_pair(acc[t][0], acc[t][1], Ah[t], Bl[0][j]);
                    mma_pair(acc[t][2], acc[t][3], Ah[t], Bl[1][j]);
                }
#pragma unroll
                for (int t = 0; t < 4; t++) if (val2[t]) {
                    mma_pair(acc[t][0], acc[t][1], Al[t], Bh[0][j]);
                    mma_pair(acc[t][2], acc[t][3], Al[t], Bh[1][j]);
                }
            }
        }
        __syncthreads();                                    // S3 (A2 dead, C2 aliasing safe)
#pragma unroll
        for (int t = 0; t < 4; t++) if (val2[t]) {
            float* C2p = (float*)(smem + SM_C2 + pim[t] * 25872);
            int pos = (mt[t] - 1) * 14 + g;
#pragma unroll
            for (int n = 0; n < 4; n++) {
                int col = n * 8 + 2 * tg;
                C2p[pos * 33 + col] = acc[t][n][0];
                C2p[pos * 33 + col + 1] = acc[t][n][1];
                if (g < 6) {
                    C2p[(pos + 8) * 33 + col] = acc[t][n][2];
                    C2p[(pos + 8) * 33 + col + 1] = acc[t][n][3];
                }
            }
        }
        __syncthreads();                                    // S4
        // ---- pool conv2 -> PO (bias+relu) ----
        for (int idx = tid; idx < 3136; idx += 256) {
            int p = idx >= 1568, i2 = idx - p * 1568;
            int oc = i2 & 31, pos = i2 >> 5;
            int pr = pos / 7, pc = pos - pr * 7;
            const float* c0 = (float*)(smem + SM_C2 + p * 25872) + ((2 * pr) * 14 + 2 * pc) * 33 + oc;
            float v = fmaxf(fmaxf(c0[0], c0[33]), fmaxf(c0[14 * 33], c0[15 * 33]));
            ((float*)(smem + SM_PO + p * 6468))[pos * 33 + oc] = fmaxf(v + __ldg(&cb2[oc]), 0.f);
        }
        __syncthreads();                                    // S5
        // ---- A3 fill ----
        for (int t = wid; t < 98; t += 8) {
            int p = t >= 49, tt = t - p * 49;
            int P = tt / 7 + 1, Q = tt - (tt / 7) * 7;
            float v = ((float*)(smem + SM_PO + p * 6468))[tt * 33 + lane];
            uint32_t off = (uint32_t)((P * 16 + Q + 1) * SAS + lane) * 2;
            uint32_t base = SM_A3 + (uint32_t)p * 21760u;
            split_store(smem, base + off, base + 10880u + off, v);
        }
        __syncthreads();                                    // S6
        // ---- conv3 mma + C3 store ----
        float acc3[3][2][4];
#pragma unroll
        for (int t = 0; t < 3; t++)
#pragma unroll
            for (int n = 0; n < 2; n++)
#pragma unroll
                for (int i = 0; i < 4; i++) acc3[t][n][i] = 0.f;
#pragma unroll
        for (int tap = 0; tap < 9; tap++) {
            uint32_t bmat = sb + SM_B + (uint32_t)(18 + tap * 2) * SB_MAT;
            uint32_t B3h[2][4], B3l[2][4];
#pragma unroll
            for (int j = 0; j < 2; j++) {
                uint32_t boff = (((uint32_t)np3 * 16 + b_row) * SAS + (uint32_t)j * 16 + b_c) * 2;
                LDSM4(B3h[j], bmat + boff);
                LDSM4(B3l[j], bmat + SB_MAT + boff);
            }
            int dr = (tap / 3 - 1) * 16 + (tap % 3 - 1) + 1;
#pragma unroll
            for (int j = 0; j < 2; j++) {
                uint32_t A3h[3][4], A3l[3][4];
#pragma unroll
                for (int t = 0; t < 3; t++) {
                    uint32_t base = sb + SM_A3 + (uint32_t)p3[t] * 21760u;
                    uint32_t aoff = (uint32_t)((mu[t] * 16 + dr + (int)a_r) * SAS) * 2
                                    + ((uint32_t)j * 16 + a_c) * 2;
                    LDSM4(A3h[t], base + aoff);
                    LDSM4(A3l[t], base + 10880u + aoff);
                }
#pragma unroll
                for (int t = 0; t < 3; t++)
                    mma_pair(acc3[t][0], acc3[t][1], A3h[t], B3h[j]);
#pragma unroll
                for (int t = 0; t < 3; t++)
                    mma_pair(acc3[t][0], acc3[t][1], A3h[t], B3l[j]);
#pragma unroll
                for (int t = 0; t < 3; t++)
                    mma_pair(acc3[t][0], acc3[t][1], A3l[t], B3h[j]);
            }
        }
        if (g < 6) {
#pragma unroll
            for (int t = 0; t < 3; t++) {
                float* C3p = (float*)(smem + SM_C3 + p3[t] * 4752);
                int pos6 = (mu[t] - 1) * 6 + g;
#pragma unroll
                for (int n = 0; n < 2; n++) {
                    int col = np3 * 16 + n * 8 + 2 * tg;
                    C3p[pos6 * 33 + col] = acc3[t][n][0];
                    C3p[pos6 * 33 + col + 1] = acc3[t][n][1];
                }
            }
        }
        __syncthreads();                                    // S7
        // ---- epilogue: pool conv3 + bias + relu -> g_out3 + BN partials ----
        for (int p = 0; p < 2; p++) {
            int img = img0 + p * 148;
            if (img >= B) break;
            float* C3p = (float*)(smem + SM_C3 + p * 4752);
            float* go = g_out3 + img * 288;
            {
                int oc = myoc, pos = tid - oc * 9;
                int pr = pos / 3, pc = pos - pr * 3;
                const float* c0 = C3p + ((2 * pr) * 6 + 2 * pc) * 33 + oc;
                float v = fmaxf(fmaxf(c0[0], c0[33]), fmaxf(c0[6 * 33], c0[7 * 33]));
                v = fmaxf(v + __ldg(&cb3[oc]), 0.f);
                go[tid] = v; lsum += v; lsq += v * v;
            }
            if (tid < 32) {
                int idx = tid + 256;
                int oc = myoc2, pos = idx - oc * 9;
                int pr = pos / 3, pc = pos - pr * 3;
                const float* c0 = C3p + ((2 * pr) * 6 + 2 * pc) * 33 + oc;
                float v = fmaxf(fmaxf(c0[0], c0[33]), fmaxf(c0[6 * 33], c0[7 * 33]));
                v = fmaxf(v + __ldg(&cb3[oc]), 0.f);
                go[idx] = v; lsum2 += v; lsq2 += v * v;
            }
        }
    }
    __syncthreads();
    atomicAdd(&ssum[myoc], lsum); atomicAdd(&ssq[myoc], lsq);
    if (tid < 32) { atomicAdd(&ssum[myoc2], lsum2); atomicAdd(&ssq[myoc2], lsq2); }
    __syncthreads();
    if (tid < 32) {
        atomicAdd(&g_stats[tid], ssum[tid]);
        atomicAdd(&g_stats[32 + tid], ssq[tid]);
    }
}

// ---------------- BN finalize ---------------------------------------------------
__global__ void bn_finalize_kernel(const float* __restrict__ bn_g,
                                   const float* __restrict__ bn_b) {
    int c = threadIdx.x;
    if (c < 32) {
        const float inv_n = 1.0f / (float)(B * 9);
        float m = g_stats[c] * inv_n;
        float var = g_stats[32 + c] * inv_n - m * m;
        float sc = bn_g[c] * rsqrtf(var + 1e-5f);
        g_scale[c] = sc;
        g_shift[c] = bn_b[c] - m * sc;
    }
}

// ---------------- compose expert chain ------------------------------------------
__global__ void compose_kernel(const float* __restrict__ ew1, const float* __restrict__ eb1,
                               const float* __restrict__ ew2, const float* __restrict__ eb2,
                               const float* __restrict__ ew3, const float* __restrict__ eb3) {
    __shared__ float E3s[1280];
    __shared__ float C1s[1280];
    int a = blockIdx.x, tid = threadIdx.x;
    for (int i = tid; i < 1280; i += 128) E3s[i] = ew3[a * 1280 + i];
    __syncthreads();
    {
        float s[10];
#pragma unroll
        for (int o = 0; o < 10; o++) s[o] = 0.f;
        const float* e2r = ew2 + a * 16384 + tid * 128;
        for (int j = 0; j < 128; j++) {
            float e = e2r[j];
#pragma unroll
            for (int o = 0; o < 10; o++) s[o] += e * E3s[j * 10 + o];
        }
#pragma unroll
        for (int o = 0; o < 10; o++) C1s[tid * 10 + o] = s[o];
    }
    __syncthreads();
    if (tid < 10) {
        float bb = eb3[a * 10 + tid];
        for (int i = 0; i < 128; i++) {
            bb += eb2[a * 128 + i] * E3s[i * 10 + tid];
            bb += eb1[a * 128 + i] * C1s[i * 10 + tid];
        }
        g_bc[a * 10 + tid] = bb;
    }
    for (int k = tid; k < 288; k += 128) {
        float s[10];
#pragma unroll
        for (int o = 0; o < 10; o++) s[o] = 0.f;
        const float* e1r = ew1 + a * 36864 + k * 128;
        for (int i = 0; i < 128; i++) {
            float e = e1r[i];
#pragma unroll
            for (int o = 0; o < 10; o++) s[o] += e * C1s[i * 10 + o];
        }
#pragma unroll
        for (int o = 0; o < 10; o++) g_Wc[(a * 288 + k) * 10 + o] = s[o];
    }
}

// ---------------- MLP + argmax + composed selection -----------------------------
__global__ void __launch_bounds__(256) mlp_kernel(
    const float* __restrict__ pw1, const float* __restrict__ pb1,
    const float* __restrict__ pw2, const float* __restrict__ pb2,
    const float* __restrict__ pw3, const float* __restrict__ pb3,
    float* __restrict__ out, int write_actions) {
    __shared__ float ys[8 * 2 * 288];
    __shared__ float hA[8 * 2 * 128];
    __shared__ float hB[8 * 2 * 128];
    int w = threadIdx.x >> 5, lane = threadIdx.x & 31;
    float* yw = ys + w * 576;
    float* ha = hA + w * 256;
    float* hb = hB + w * 256;
    int e0 = blockIdx.x * 16 + w * 2;

    for (int idx = lane; idx < 576; idx += 32) {
        int e = idx / 288, k = idx - e * 288, c = k / 9;
        yw[idx] = g_out3[(e0 + e) * 288 + k] * g_scale[c] + g_shift[c];
    }
    __syncwarp();
    {
        float acc[2][4];
#pragma unroll
        for (int m = 0; m < 4; m++) {
            float bv = __ldg(&pb1[lane + 32 * m]);
            acc[0][m] = bv; acc[1][m] = bv;
        }
        for (int k = 0; k < 288; k++) {
            const float* wr = pw1 + k * 128 + lane;
            float w0 = wr[0], w1 = wr[32], w2 = wr[64], w3 = wr[96];
            float y0 = yw[k], y1 = yw[288 + k];
            acc[0][0] += y0 * w0; acc[0][1] += y0 * w1; acc[0][2] += y0 * w2; acc[0][3] += y0 * w3;
            acc[1][0] += y1 * w0; acc[1][1] += y1 * w1; acc[1][2] += y1 * w2; acc[1][3] += y1 * w3;
        }
#pragma unroll
        for (int e = 0; e < 2; e++)
#pragma unroll
            for (int m = 0; m < 4; m++)
                ha[e * 128 + lane + 32 * m] = fmaxf(acc[e][m], 0.f);
    }
    __syncwarp();
    {
        float acc[2][4];
#pragma unroll
        for (int m = 0; m < 4; m++) {
            float bv = __ldg(&pb2[lane + 32 * m]);
            acc[0][m] = bv; acc[1][m] = bv;
        }
        for (int k = 0; k < 128; k++) {
            const float* wr = pw2 + k * 128 + lane;
            float w0 = wr[0], w1 = wr[32], w2 = wr[64], w3 = wr[96];
            float y0 = ha[k], y1 = ha[128 + k];
            acc[0][0] += y0 * w0; acc[0][1] += y0 * w1; acc[0][2] += y0 * w2; acc[0][3] += y0 * w3;
            acc[1][0] += y1 * w0; acc[1][1] += y1 * w1; acc[1][2] += y1 * w2; acc[1][3] += y1 * w3;
        }
#pragma unroll
        for (int e = 0; e < 2; e++)
#pragma unroll
            for (int m = 0; m < 4; m++)
                hb[e * 128 + lane + 32 * m] = fmaxf(acc[e][m], 0.f);
    }
    __syncwarp();
    for (int e = 0; e < 2; e++) {
        float p0 = 0.f, p1 = 0.f, p2 = 0.f;
#pragma unroll
        for (int kk = 0; kk < 4; kk++) {
            int k = lane + 32 * kk;
            float hv = hb[e * 128 + k];
            const float* wr = pw3 + k * 3;
            p0 += hv * wr[0]; p1 += hv * wr[1]; p2 += hv * wr[2];
        }
#pragma unroll
        for (int off = 16; off > 0; off >>= 1) {
            p0 += __shfl_down_sync(0xffffffffu, p0, off);
            p1 += __shfl_down_sync(0xffffffffu, p1, off);
            p2 += __shfl_down_sync(0xffffffffu, p2, off);
        }
        int a = 0;
        if (lane == 0) {
            p0 += __ldg(&pb3[0]); p1 += __ldg(&pb3[1]); p2 += __ldg(&pb3[2]);
            float best = p0;
            if (p1 > best) { best = p1; a = 1; }
            if (p2 > best) { a = 2; }
        }
        a = __shfl_sync(0xffffffffu, a, 0);
        float po[10];
#pragma unroll
        for (int o = 0; o < 10; o++) po[o] = 0.f;
        const float* Wb = g_Wc + a * 2880;
        const float* ye = yw + e * 288;
#pragma unroll
        for (int kk = 0; kk < 9; kk++) {
            int k = lane + 32 * kk;
            float yv = ye[k];
            const float* wr = Wb + k * 10;
#pragma unroll
            for (int o = 0; o < 10; o++) po[o] += yv * wr[o];
        }
#pragma unroll
        for (int off = 16; off > 0; off >>= 1) {
#pragma unroll
            for (int o = 0; o < 10; o++) po[o] += __shfl_down_sync(0xffffffffu, po[o], off);
        }
        if (lane == 0) {
            int g = e0 + e;
#pragma unroll
            for (int o = 0; o < 10; o++) out[g * 10 + o] = po[o] + g_bc[a * 10 + o];
            if (write_actions) out[B * 10 + g] = (float)a;
        }
    }
}

// ---------------- launch --------------------------------------------------------
extern "C" void kernel_launch(void* const* d_in, const int* in_sizes, int n_in,
                              void* d_out, int out_size) {
    const float* x    = (const float*)d_in[0];
    const float* cw1  = (const float*)d_in[1];
    const float* cb1  = (const float*)d_in[2];
    const float* cw2  = (const float*)d_in[3];
    const float* cb2  = (const float*)d_in[4];
    const float* cw3  = (const float*)d_in[5];
    const float* cb3  = (const float*)d_in[6];
    const float* bn_g = (const float*)d_in[7];
    const float* bn_b = (const float*)d_in[8];
    const float* pw1  = (const float*)d_in[9];
    const float* pb1  = (const float*)d_in[10];
    const float* pw2  = (const float*)d_in[11];
    const float* pb2  = (const float*)d_in[12];
    const float* pw3  = (const float*)d_in[13];
    const float* pb3  = (const float*)d_in[14];
    const float* ew1  = (const float*)d_in[15];
    const float* eb1  = (const float*)d_in[16];
    const float* ew2  = (const float*)d_in[17];
    const float* eb2  = (const float*)d_in[18];
    const float* ew3  = (const float*)d_in[19];
    const float* eb3  = (const float*)d_in[20];
    float* out = (float*)d_out;
    int write_actions = (out_size >= B * 10 + B) ? 1 : 0;

    cudaFuncSetAttribute(conv23_kernel, cudaFuncAttributeMaxDynamicSharedMemorySize, SM_TOTAL);

    zero_stats_kernel<<<1, 64>>>();
    conv1_kernel<<<(B * 196) / 256, 256>>>(x, cw1, cb1);
    conv23_kernel<<<148, 256, SM_TOTAL>>>(cw2, cb2, cw3, cb3);
    bn_finalize_kernel<<<1, 32>>>(bn_g, bn_b);
    compose_kernel<<<3, 128>>>(ew1, eb1, ew2, eb2, ew3, eb3);
    mlp_kernel<<<B / 16, 256>>>(pw1, pb1, pw2, pb2, pw3, pb3, out, write_actions);
}

// round 7
// speedup vs baseline: 1.7103x; 1.2979x over previous
#include <cuda_runtime.h>
#include <cuda_bf16.h>
#include <cuda_fp16.h>
#include <cstdint>

#define B 4096

__device__ __half g1h[B * 6272];     // conv1 out hi-half, [b][pos][ic]
__device__ __half g1l[B * 6272];     // conv1 out lo-half
__device__ float g_out3[B * 288];    // conv3 out (pre-BN), [b][oc*9+pos]
__device__ float g_stats[64];
__device__ float g_scale[32], g_shift[32];
__device__ float g_Wc[3 * 288 * 10];
__device__ float g_bc[30];

// ---------------- portable tensor-core helpers (sm_80+ PTX only) ---------------
__device__ __forceinline__ uint32_t smem_u32(const void* p) {
    uint32_t a;
    asm("{ .reg .u64 t; cvta.to.shared.u64 t, %1; cvt.u32.u64 %0, t; }" : "=r"(a) : "l"(p));
    return a;
}
#define LDSM4(r, addr) \
    asm volatile("ldmatrix.sync.aligned.m8n8.x4.shared.b16 {%0,%1,%2,%3}, [%4];" \
                 : "=r"((r)[0]), "=r"((r)[1]), "=r"((r)[2]), "=r"((r)[3]) : "r"(addr))
__device__ __forceinline__ void mma16816(float* c, const uint32_t a[4], uint32_t b0, uint32_t b1) {
    asm volatile("mma.sync.aligned.m16n8k16.row.col.f32.f16.f16.f32 "
                 "{%0,%1,%2,%3}, {%4,%5,%6,%7}, {%8,%9}, {%0,%1,%2,%3};"
                 : "+f"(c[0]), "+f"(c[1]), "+f"(c[2]), "+f"(c[3])
                 : "r"(a[0]), "r"(a[1]), "r"(a[2]), "r"(a[3]), "r"(b0), "r"(b1));
}
__device__ __forceinline__ void mma_pair(float* c0, float* c1, const uint32_t a[4], const uint32_t b[4]) {
    mma16816(c0, a, b[0], b[1]);
    mma16816(c1, a, b[2], b[3]);
}
__device__ __forceinline__ void split_store(char* smem, uint32_t oh, uint32_t ol, float v) {
    __half h = __float2half_rn(v);
    __half l = __float2half_rn(v - __half2float(h));
    *(__half*)(smem + oh) = h;
    *(__half*)(smem + ol) = l;
}
#define CP_COMMIT asm volatile("cp.async.commit_group;")
#define CP_WAIT0  asm volatile("cp.async.wait_group 0;" ::: "memory")

__global__ void zero_stats_kernel() { if (threadIdx.x < 64) g_stats[threadIdx.x] = 0.f; }

// ---------------- conv1 (1->32)+relu+pool -> split halves [b][pos][ic] ----------
__global__ void conv1_kernel(const float* __restrict__ x,
                             const float* __restrict__ cw1,
                             const float* __restrict__ cb1) {
    __shared__ float w1s[288], b1s[32];
    int tid = threadIdx.x;
    for (int i = tid; i < 288; i += 256) w1s[i] = cw1[i];
    if (tid < 32) b1s[tid] = cb1[tid];
    __syncthreads();
    int idx = blockIdx.x * 256 + tid;
    int b = idx / 196, pos = idx - b * 196;
    int ph = pos / 14, pw = pos - ph * 14;
    float p[4][4];
    const float* xb = x + b * 784;
#pragma unroll
    for (int r = 0; r < 4; r++) {
        int ir = 2 * ph - 1 + r;
#pragma unroll
        for (int c = 0; c < 4; c++) {
            int ic = 2 * pw - 1 + c;
            p[r][c] = (ir >= 0 && ir < 28 && ic >= 0 && ic < 28) ? xb[ir * 28 + ic] : 0.f;
        }
    }
    __half2 vh[16], vl[16];
#pragma unroll 4
    for (int oc = 0; oc < 32; oc += 2) {
        float vv[2];
#pragma unroll
        for (int s = 0; s < 2; s++) {
            float a0 = 0.f, a1 = 0.f, a2 = 0.f, a3 = 0.f;
#pragma unroll
            for (int kh = 0; kh < 3; kh++)
#pragma unroll
                for (int kw = 0; kw < 3; kw++) {
                    float w = w1s[(oc + s) * 9 + kh * 3 + kw];
                    a0 += p[kh][kw] * w;     a1 += p[kh][kw + 1] * w;
                    a2 += p[kh + 1][kw] * w; a3 += p[kh + 1][kw + 1] * w;
                }
            vv[s] = fmaxf(fmaxf(fmaxf(a0, a1), fmaxf(a2, a3)) + b1s[oc + s], 0.f);
        }
        __half h0 = __float2half_rn(vv[0]), h1 = __float2half_rn(vv[1]);
        vh[oc >> 1] = __halves2half2(h0, h1);
        vl[oc >> 1] = __halves2half2(__float2half_rn(vv[0] - __half2float(h0)),
                                     __float2half_rn(vv[1] - __half2float(h1)));
    }
    uint4* dh = (uint4*)(g1h + (size_t)(b * 196 + pos) * 32);
    uint4* dl = (uint4*)(g1l + (size_t)(b * 196 + pos) * 32);
#pragma unroll
    for (int j = 0; j < 4; j++) {
        dh[j] = ((uint4*)vh)[j];
        dl[j] = ((uint4*)vl)[j];
    }
}

// ---------------- fused conv2+conv3, pipelined (cp.async double buffer) ---------
#define SAS 40
#define SM_A2_0 1024
#define SM_A2_1 41984
#define SM_A3   82944        // hi 6400 | lo 6400 (80 rows x 80B)
#define SM_B    95744        // 36 x 2560
#define SB_MAT  2560
#define SM_PO   187904       // 49*33*4 = 6468
#define SM_C3   194372       // 36*33*4 = 4752
#define SM_TOTAL 199168

__device__ __forceinline__ void prefetch_img(uint32_t sb, uint32_t bufbase, int img, int tid) {
    const char* srcH = (const char*)(g1h + (size_t)img * 6272);
    const char* srcL = (const char*)(g1l + (size_t)img * 6272);
    for (int c = tid; c < 1568; c += 256) {
        int t = c >> 3, rem = c & 7;
        int part = rem >> 2, seg = rem & 3;
        int tt = t / 14;
        int P = tt + 1, Q = t - tt * 14;
        uint32_t dst = sb + bufbase + (uint32_t)part * 20480u
                       + (uint32_t)((P * 16 + Q + 1) * 80 + seg * 16);
        const char* src = (part ? srcL : srcH) + (size_t)(t * 32 + seg * 8) * 2;
        asm volatile("cp.async.ca.shared.global [%0], [%1], 16;" :: "r"(dst), "l"(src));
    }
}

__device__ __forceinline__ void zero_pads(char* smem, uint32_t bufbase, int tid) {
    for (int z = tid; z < 600; z += 256) {
        int si = z / 300, r = z - si * 300;
        int ri = r / 5, q = r - ri * 5;
        int row;
        if (ri < 17) row = ri;
        else if (ri < 43) { int k = ri - 17; row = (k >> 1) * 16 + 31 + (k & 1); }
        else row = 239 + (ri - 43);
        *(float4*)(smem + bufbase + si * 20480 + row * 80 + q * 16) =
            make_float4(0.f, 0.f, 0.f, 0.f);
    }
}

__global__ void __launch_bounds__(256, 1) conv23_kernel(
    const float* __restrict__ cw2, const float* __restrict__ cb2,
    const float* __restrict__ cw3, const float* __restrict__ cb3) {
    extern __shared__ char smem[];
    uint32_t sb = smem_u32(smem);
    int tid = threadIdx.x, wid = tid >> 5, lane = tid & 31;
    float* ssum = (float*)(smem + 64);
    float* ssq  = (float*)(smem + 192);
    float* PO = (float*)(smem + SM_PO);
    float* C3 = (float*)(smem + SM_C3);

    if (tid < 32) { ssum[tid] = 0.f; ssq[tid] = 0.f; }
    // zero A3 region (12800 B)
    for (int i = tid; i < 800; i += 256)
        ((float4*)(smem + SM_A3))[i] = make_float4(0.f, 0.f, 0.f, 0.f);
    zero_pads(smem, SM_A2_0, tid);
    // B fill: [conv][tap][split][oc][ic]
    for (int idx = tid; idx < 18432; idx += 256) {
        int conv = idx / 9216, r = idx % 9216;
        int tap = r / 1024, r2 = r % 1024;
        int oc = r2 >> 5, ic = r2 & 31;
        int kh = tap / 3, kw = tap % 3;
        float w = __ldg(&(conv ? cw3 : cw2)[oc * 288 + ic * 9 + kh * 3 + kw]);
        uint32_t bh = SM_B + (uint32_t)((conv * 9 + tap) * 2) * SB_MAT + (oc * SAS + ic) * 2;
        split_store(smem, bh, bh + SB_MAT, w);
    }
    // prefetch first image into buffer 0
    prefetch_img(sb, SM_A2_0, blockIdx.x, tid);
    CP_COMMIT;
    CP_WAIT0;
    __syncthreads();

    int g = lane >> 2, tg = lane & 3;
    uint32_t a_r = (uint32_t)(lane & 15), a_c = (uint32_t)((lane >> 4) * 8);
    uint32_t b_row = (uint32_t)(((lane >> 4) << 3) + (lane & 7));
    uint32_t b_c = (uint32_t)((lane & 8) ? 8 : 0);
    float lsum = 0.f, lsq = 0.f, lsum2 = 0.f, lsq2 = 0.f;
    int myoc = tid / 9, myoc2 = (tid + 256) / 9;
    // conv2 tiles: wt = wid, wid+8  (m = wt+1, valid wt<14)
    int mt[2] = { wid + 1, wid + 9 };
    int val2[2] = { 1, wid + 8 < 14 };
    // conv3 unit: tile tnum, col-pair np3 (valid wid<6)
    int tnum = wid >> 1, np3 = wid & 1;

    for (int it = 0; it < 28; it++) {
        int img = blockIdx.x + 148 * it;
        int active = img < B;
        uint32_t curb = (it & 1) ? SM_A2_1 : SM_A2_0;
        uint32_t nxtb = (it & 1) ? SM_A2_0 : SM_A2_1;
        // ---- prefetch next image (overlaps with mma below) ----
        if (it < 27) {
            zero_pads(smem, nxtb, tid);
            int imgN = img + 148;
            if (imgN < B) prefetch_img(sb, nxtb, imgN, tid);
        }
        CP_COMMIT;
        // ---- conv2 mma on cur ----
        float acc[2][4][4];
#pragma unroll
        for (int t = 0; t < 2; t++)
#pragma unroll
            for (int n = 0; n < 4; n++)
#pragma unroll
                for (int i = 0; i < 4; i++) acc[t][n][i] = 0.f;
#pragma unroll
        for (int tap = 0; tap < 9; tap++) {
            uint32_t bmat = sb + SM_B + (uint32_t)(tap * 2) * SB_MAT;
            uint32_t Bh[2][2][4], Bl[2][2][4];
#pragma unroll
            for (int np = 0; np < 2; np++)
#pragma unroll
                for (int j = 0; j < 2; j++) {
                    uint32_t boff = (((uint32_t)np * 16 + b_row) * SAS + (uint32_t)j * 16 + b_c) * 2;
                    LDSM4(Bh[np][j], bmat + boff);
                    LDSM4(Bl[np][j], bmat + SB_MAT + boff);
                }
            int dr = (tap / 3 - 1) * 16 + (tap % 3 - 1) + 1;
#pragma unroll
            for (int j = 0; j < 2; j++) {
                uint32_t Ah[2][4], Al[2][4];
#pragma unroll
                for (int t = 0; t < 2; t++) {
                    uint32_t aoff = (uint32_t)((mt[t] * 16 + dr + (int)a_r) * SAS) * 2
                                    + ((uint32_t)j * 16 + a_c) * 2;
                    LDSM4(Ah[t], sb + curb + aoff);
                    LDSM4(Al[t], sb + curb + 20480u + aoff);
                }
#pragma unroll
                for (int t = 0; t < 2; t++) if (val2[t]) {
                    mma_pair(acc[t][0], acc[t][1], Ah[t], Bh[0][j]);
                    mma_pair(acc[t][2], acc[t][3], Ah[t], Bh[1][j]);
                }
#pragma unroll
                for (int t = 0; t < 2; t++) if (val2[t]) {
                    mma_pair(acc[t][0], acc[t][1], Ah[t], Bl[0][j]);
                    mma_pair(acc[t][2], acc[t][3], Ah[t], Bl[1][j]);
                }
#pragma unroll
                for (int t = 0; t < 2; t++) if (val2[t]) {
                    mma_pair(acc[t][0], acc[t][1], Al[t], Bh[0][j]);
                    mma_pair(acc[t][2], acc[t][3], Al[t], Bh[1][j]);
                }
            }
        }
        __syncthreads();                                     // S1: cur reads done
        // C2 aliases cur buffer
        float* C2 = (float*)(smem + curb);
#pragma unroll
        for (int t = 0; t < 2; t++) if (val2[t]) {
            int pos = (mt[t] - 1) * 14 + g;
#pragma unroll
            for (int n = 0; n < 4; n++) {
                int col = n * 8 + 2 * tg;
                C2[pos * 33 + col] = acc[t][n][0];
                C2[pos * 33 + col + 1] = acc[t][n][1];
                if (g < 6) {
                    C2[(pos + 8) * 33 + col] = acc[t][n][2];
                    C2[(pos + 8) * 33 + col + 1] = acc[t][n][3];
                }
            }
        }
        __syncthreads();                                     // S2
        // pool conv2 -> PO (bias+relu)
        for (int idx = tid; idx < 1568; idx += 256) {
            int oc = idx & 31, pos = idx >> 5;
            int pr = pos / 7, pc = pos - pr * 7;
            const float* c0 = C2 + ((2 * pr) * 14 + 2 * pc) * 33 + oc;
            float v = fmaxf(fmaxf(c0[0], c0[33]), fmaxf(c0[14 * 33], c0[15 * 33]));
            PO[pos * 33 + oc] = fmaxf(v + __ldg(&cb2[oc]), 0.f);
        }
        __syncthreads();                                     // S3
        // A3 fill (8-row pack): row = (r+2)*8 + c
        for (int t = wid; t < 49; t += 8) {
            int r = t / 7, c = t - r * 7;
            int row = (r + 2) * 8 + c;
            float v = PO[t * 33 + lane];
            uint32_t off = (uint32_t)(row * SAS + lane) * 2;
            split_store(smem, SM_A3 + off, SM_A3 + 6400 + off, v);
        }
        __syncthreads();                                     // S4
        // conv3 mma (3 tiles x 2 np, warps 0-5)
        if (wid < 6) {
            float acc3[2][2][4];
#pragma unroll
            for (int bk = 0; bk < 2; bk++)
#pragma unroll
                for (int n = 0; n < 2; n++)
#pragma unroll
                    for (int i = 0; i < 4; i++) acc3[bk][n][i] = 0.f;
            int base = 16 + tnum * 16;
#pragma unroll
            for (int tap = 0; tap < 9; tap++) {
                uint32_t bmat = sb + SM_B + (uint32_t)(18 + tap * 2) * SB_MAT;
                uint32_t B3h[2][4], B3l[2][4];
#pragma unroll
                for (int j = 0; j < 2; j++) {
                    uint32_t boff = (((uint32_t)np3 * 16 + b_row) * SAS + (uint32_t)j * 16 + b_c) * 2;
                    LDSM4(B3h[j], bmat + boff);
                    LDSM4(B3l[j], bmat + SB_MAT + boff);
                }
                int dr3 = (tap / 3 - 1) * 8 + (tap % 3 - 1);
#pragma unroll
                for (int j = 0; j < 2; j++) {
                    uint32_t aoff = (uint32_t)((base + dr3 + (int)a_r) * SAS) * 2
                                    + ((uint32_t)j * 16 + a_c) * 2;
                    uint32_t A3h[4], A3l[4];
                    LDSM4(A3h, sb + SM_A3 + aoff);
                    LDSM4(A3l, sb + SM_A3 + 6400u + aoff);
                    mma_pair(acc3[j][0], acc3[j][1], A3h, B3h[j]);
                    mma_pair(acc3[j ^ 1][0], acc3[j ^ 1][1], A3h, B3l[j]);
                    mma_pair(acc3[j][0], acc3[j][1], A3l, B3h[j]);
                }
            }
            if (g < 6) {
#pragma unroll
                for (int n = 0; n < 2; n++) {
                    int col = np3 * 16 + n * 8 + 2 * tg;
                    int pos0 = (2 * tnum) * 6 + g;
                    int pos1 = (2 * tnum + 1) * 6 + g;
                    C3[pos0 * 33 + col] = acc3[0][n][0] + acc3[1][n][0];
                    C3[pos0 * 33 + col + 1] = acc3[0][n][1] + acc3[1][n][1];
                    C3[pos1 * 33 + col] = acc3[0][n][2] + acc3[1][n][2];
                    C3[pos1 * 33 + col + 1] = acc3[0][n][3] + acc3[1][n][3];
                }
            }
        }
        __syncthreads();                                     // S5
        // epilogue: pool conv3 + bias + relu -> g_out3 + BN partials
        if (active) {
            float* go = g_out3 + img * 288;
            {
                int oc = myoc, pos = tid - oc * 9;
                int pr = pos / 3, pc = pos - pr * 3;
                const float* c0 = C3 + ((2 * pr) * 6 + 2 * pc) * 33 + oc;
                float v = fmaxf(fmaxf(c0[0], c0[33]), fmaxf(c0[6 * 33], c0[7 * 33]));
                v = fmaxf(v + __ldg(&cb3[oc]), 0.f);
                go[tid] = v; lsum += v; lsq += v * v;
            }
            if (tid < 32) {
                int idx = tid + 256;
                int oc = myoc2, pos = idx - oc * 9;
                int pr = pos / 3, pc = pos - pr * 3;
                const float* c0 = C3 + ((2 * pr) * 6 + 2 * pc) * 33 + oc;
                float v = fmaxf(fmaxf(c0[0], c0[33]), fmaxf(c0[6 * 33], c0[7 * 33]));
                v = fmaxf(v + __ldg(&cb3[oc]), 0.f);
                go[idx] = v; lsum2 += v; lsq2 += v * v;
            }
        }
        CP_WAIT0;
        __syncthreads();                                     // S6: next buffer ready
    }
    atomicAdd(&ssum[myoc], lsum); atomicAdd(&ssq[myoc], lsq);
    if (tid < 32) { atomicAdd(&ssum[myoc2], lsum2); atomicAdd(&ssq[myoc2], lsq2); }
    __syncthreads();
    if (tid < 32) {
        atomicAdd(&g_stats[tid], ssum[tid]);
        atomicAdd(&g_stats[32 + tid], ssq[tid]);
    }
}

// ---------------- BN finalize ---------------------------------------------------
__global__ void bn_finalize_kernel(const float* __restrict__ bn_g,
                                   const float* __restrict__ bn_b) {
    int c = threadIdx.x;
    if (c < 32) {
        const float inv_n = 1.0f / (float)(B * 9);
        float m = g_stats[c] * inv_n;
        float var = g_stats[32 + c] * inv_n - m * m;
        float sc = bn_g[c] * rsqrtf(var + 1e-5f);
        g_scale[c] = sc;
        g_shift[c] = bn_b[c] - m * sc;
    }
}

// ---------------- compose expert chain ------------------------------------------
__global__ void compose_kernel(const float* __restrict__ ew1, const float* __restrict__ eb1,
                               const float* __restrict__ ew2, const float* __restrict__ eb2,
                               const float* __restrict__ ew3, const float* __restrict__ eb3) {
    __shared__ float E3s[1280];
    __shared__ float C1s[1280];
    int a = blockIdx.x, tid = threadIdx.x;
    for (int i = tid; i < 1280; i += 128) E3s[i] = ew3[a * 1280 + i];
    __syncthreads();
    {
        float s[10];
#pragma unroll
        for (int o = 0; o < 10; o++) s[o] = 0.f;
        const float* e2r = ew2 + a * 16384 + tid * 128;
        for (int j = 0; j < 128; j++) {
            float e = e2r[j];
#pragma unroll
            for (int o = 0; o < 10; o++) s[o] += e * E3s[j * 10 + o];
        }
#pragma unroll
        for (int o = 0; o < 10; o++) C1s[tid * 10 + o] = s[o];
    }
    __syncthreads();
    if (tid < 10) {
        float bb = eb3[a * 10 + tid];
        for (int i = 0; i < 128; i++) {
            bb += eb2[a * 128 + i] * E3s[i * 10 + tid];
            bb += eb1[a * 128 + i] * C1s[i * 10 + tid];
        }
        g_bc[a * 10 + tid] = bb;
    }
    for (int k = tid; k < 288; k += 128) {
        float s[10];
#pragma unroll
        for (int o = 0; o < 10; o++) s[o] = 0.f;
        const float* e1r = ew1 + a * 36864 + k * 128;
        for (int i = 0; i < 128; i++) {
            float e = e1r[i];
#pragma unroll
            for (int o = 0; o < 10; o++) s[o] += e * C1s[i * 10 + o];
        }
#pragma unroll
        for (int o = 0; o < 10; o++) g_Wc[(a * 288 + k) * 10 + o] = s[o];
    }
}

// ---------------- MLP + argmax + composed selection -----------------------------
__global__ void __launch_bounds__(256) mlp_kernel(
    const float* __restrict__ pw1, const float* __restrict__ pb1,
    const float* __restrict__ pw2, const float* __restrict__ pb2,
    const float* __restrict__ pw3, const float* __restrict__ pb3,
    float* __restrict__ out, int write_actions) {
    __shared__ float ys[8 * 2 * 288];
    __shared__ float hA[8 * 2 * 128];
    __shared__ float hB[8 * 2 * 128];
    int w = threadIdx.x >> 5, lane = threadIdx.x & 31;
    float* yw = ys + w * 576;
    float* ha = hA + w * 256;
    float* hb = hB + w * 256;
    int e0 = blockIdx.x * 16 + w * 2;

    for (int idx = lane; idx < 576; idx += 32) {
        int e = idx / 288, k = idx - e * 288, c = k / 9;
        yw[idx] = g_out3[(e0 + e) * 288 + k] * g_scale[c] + g_shift[c];
    }
    __syncwarp();
    {
        float acc[2][4];
#pragma unroll
        for (int m = 0; m < 4; m++) {
            float bv = __ldg(&pb1[lane + 32 * m]);
            acc[0][m] = bv; acc[1][m] = bv;
        }
        for (int k = 0; k < 288; k++) {
            const float* wr = pw1 + k * 128 + lane;
            float w0 = wr[0], w1 = wr[32], w2 = wr[64], w3 = wr[96];
            float y0 = yw[k], y1 = yw[288 + k];
            acc[0][0] += y0 * w0; acc[0][1] += y0 * w1; acc[0][2] += y0 * w2; acc[0][3] += y0 * w3;
            acc[1][0] += y1 * w0; acc[1][1] += y1 * w1; acc[1][2] += y1 * w2; acc[1][3] += y1 * w3;
        }
#pragma unroll
        for (int e = 0; e < 2; e++)
#pragma unroll
            for (int m = 0; m < 4; m++)
                ha[e * 128 + lane + 32 * m] = fmaxf(acc[e][m], 0.f);
    }
    __syncwarp();
    {
        float acc[2][4];
#pragma unroll
        for (int m = 0; m < 4; m++) {
            float bv = __ldg(&pb2[lane + 32 * m]);
            acc[0][m] = bv; acc[1][m] = bv;
        }
        for (int k = 0; k < 128; k++) {
            const float* wr = pw2 + k * 128 + lane;
            float w0 = wr[0], w1 = wr[32], w2 = wr[64], w3 = wr[96];
            float y0 = ha[k], y1 = ha[128 + k];
            acc[0][0] += y0 * w0; acc[0][1] += y0 * w1; acc[0][2] += y0 * w2; acc[0][3] += y0 * w3;
            acc[1][0] += y1 * w0; acc[1][1] += y1 * w1; acc[1][2] += y1 * w2; acc[1][3] += y1 * w3;
        }
#pragma unroll
        for (int e = 0; e < 2; e++)
#pragma unroll
            for (int m = 0; m < 4; m++)
                hb[e * 128 + lane + 32 * m] = fmaxf(acc[e][m], 0.f);
    }
    __syncwarp();
    for (int e = 0; e < 2; e++) {
        float p0 = 0.f, p1 = 0.f, p2 = 0.f;
#pragma unroll
        for (int kk = 0; kk < 4; kk++) {
            int k = lane + 32 * kk;
            float hv = hb[e * 128 + k];
            const float* wr = pw3 + k * 3;
            p0 += hv * wr[0]; p1 += hv * wr[1]; p2 += hv * wr[2];
        }
#pragma unroll
        for (int off = 16; off > 0; off >>= 1) {
            p0 += __shfl_down_sync(0xffffffffu, p0, off);
            p1 += __shfl_down_sync(0xffffffffu, p1, off);
            p2 += __shfl_down_sync(0xffffffffu, p2, off);
        }
        int a = 0;
        if (lane == 0) {
            p0 += __ldg(&pb3[0]); p1 += __ldg(&pb3[1]); p2 += __ldg(&pb3[2]);
            float best = p0;
            if (p1 > best) { best = p1; a = 1; }
            if (p2 > best) { a = 2; }
        }
        a = __shfl_sync(0xffffffffu, a, 0);
        float po[10];
#pragma unroll
        for (int o = 0; o < 10; o++) po[o] = 0.f;
        const float* Wb = g_Wc + a * 2880;
        const float* ye = yw + e * 288;
#pragma unroll
        for (int kk = 0; kk < 9; kk++) {
            int k = lane + 32 * kk;
            float yv = ye[k];
            const float* wr = Wb + k * 10;
#pragma unroll
            for (int o = 0; o < 10; o++) po[o] += yv * wr[o];
        }
#pragma unroll
        for (int off = 16; off > 0; off >>= 1) {
#pragma unroll
            for (int o = 0; o < 10; o++) po[o] += __shfl_down_sync(0xffffffffu, po[o], off);
        }
        if (lane == 0) {
            int g = e0 + e;
#pragma unroll
            for (int o = 0; o < 10; o++) out[g * 10 + o] = po[o] + g_bc[a * 10 + o];
            if (write_actions) out[B * 10 + g] = (float)a;
        }
    }
}

// ---------------- launch --------------------------------------------------------
extern "C" void kernel_launch(void* const* d_in, const int* in_sizes, int n_in,
                              void* d_out, int out_size) {
    const float* x    = (const float*)d_in[0];
    const float* cw1  = (const float*)d_in[1];
    const float* cb1  = (const float*)d_in[2];
    const float* cw2  = (const float*)d_in[3];
    const float* cb2  = (const float*)d_in[4];
    const float* cw3  = (const float*)d_in[5];
    const float* cb3  = (const float*)d_in[6];
    const float* bn_g = (const float*)d_in[7];
    const float* bn_b = (const float*)d_in[8];
    const float* pw1  = (const float*)d_in[9];
    const float* pb1  = (const float*)d_in[10];
    const float* pw2  = (const float*)d_in[11];
    const float* pb2  = (const float*)d_in[12];
    const float* pw3  = (const float*)d_in[13];
    const float* pb3  = (const float*)d_in[14];
    const float* ew1  = (const float*)d_in[15];
    const float* eb1  = (const float*)d_in[16];
    const float* ew2  = (const float*)d_in[17];
    const float* eb2  = (const float*)d_in[18];
    const float* ew3  = (const float*)d_in[19];
    const float* eb3  = (const float*)d_in[20];
    float* out = (float*)d_out;
    int write_actions = (out_size >= B * 10 + B) ? 1 : 0;

    cudaFuncSetAttribute(conv23_kernel, cudaFuncAttributeMaxDynamicSharedMemorySize, SM_TOTAL);

    zero_stats_kernel<<<1, 64>>>();                              // launch 1
    conv1_kernel<<<(B * 196) / 256, 256>>>(x, cw1, cb1);          // launch 2
    zero_stats_kernel<<<1, 64>>>();                              // launch 3 (dummy: puts conv23 in profiled slot 4)
    conv23_kernel<<<148, 256, SM_TOTAL>>>(cw2, cb2, cw3, cb3);    // launch 4
    bn_finalize_kernel<<<1, 32>>>(bn_g, bn_b);
    compose_kernel<<<3, 128>>>(ew1, eb1, ew2, eb2, ew3, eb3);
    mlp_kernel<<<B / 16, 256>>>(pw1, pb1, pw2, pb2, pw3, pb3, out, write_actions);
}